// round 13
// baseline (speedup 1.0000x reference)
#include <cuda_runtime.h>
#include <cuda_fp16.h>
#include <math.h>
#include <stdint.h>

#define LAYERS 4
#define BATCH  64
#define NTOK   196
#define CDIM   768
#define CNEW   960
#define HIDDIM 3072
#define NHEAD  12
#define HD     64
#define HDK    80
#define MTOK   49
#define HW     14
#define ROWS_X (BATCH * NTOK)   // 12544
#define ROWS_R (BATCH * MTOK)   // 3136
#define NKV    (CNEW + CDIM)    // 1728

// ---------------- scratch ----------------
__device__ float g_r0[ROWS_R * CNEW];
__device__ __align__(16) __half g_yh[ROWS_X * CDIM];
__device__ __align__(16) __half g_rch[ROWS_R * CDIM];
__device__ __align__(16) __half g_rh[ROWS_R * CNEW];
__device__ __align__(16) __half g_qh[ROWS_X * CNEW];
__device__ __align__(16) __half g_kh[ROWS_R * CNEW];
__device__ __align__(16) __half g_vh[ROWS_R * CDIM];
__device__ __align__(16) __half g_oh[ROWS_X * CDIM];
__device__ __align__(16) __half g_hh[ROWS_X * HIDDIM];

// transposed weights, [N][K] K-major fp16
__device__ __align__(16) __half g_wq [LAYERS*CNEW*CDIM];
__device__ __align__(16) __half g_wpw[LAYERS*CNEW*CDIM];
__device__ __align__(16) __half g_wkv[LAYERS*NKV*CNEW];
__device__ __align__(16) __half g_wp [LAYERS*CDIM*CDIM];
__device__ __align__(16) __half g_w1 [LAYERS*HIDDIM*CDIM];
__device__ __align__(16) __half g_w2 [LAYERS*CDIM*HIDDIM];

// ---------------- helpers ----------------
__device__ __forceinline__ uint32_t smem_u32(const void* p) {
    uint32_t a;
    asm("{ .reg .u64 t; cvta.to.shared.u64 t, %1; cvt.u32.u64 %0, t; }" : "=r"(a) : "l"(p));
    return a;
}
__device__ __forceinline__ void cp16(uint32_t dst, const void* src) {
    asm volatile("cp.async.cg.shared.global [%0], [%1], 16;" :: "r"(dst), "l"(src));
}
__device__ __forceinline__ void cp_commit() { asm volatile("cp.async.commit_group;" ::: "memory"); }
template <int N> __device__ __forceinline__ void cp_wait() {
    asm volatile("cp.async.wait_group %0;" :: "n"(N) : "memory");
}
__device__ __forceinline__ void ldsm_x4(uint32_t (&r)[4], uint32_t addr) {
    asm volatile("ldmatrix.sync.aligned.m8n8.x4.shared.b16 {%0,%1,%2,%3}, [%4];"
        : "=r"(r[0]), "=r"(r[1]), "=r"(r[2]), "=r"(r[3]) : "r"(addr));
}
__device__ __forceinline__ void mma16816(float (&d)[4], const uint32_t (&a)[4],
                                         uint32_t b0, uint32_t b1) {
    asm volatile("mma.sync.aligned.m16n8k16.row.col.f32.f16.f16.f32 "
        "{%0,%1,%2,%3}, {%4,%5,%6,%7}, {%8,%9}, {%0,%1,%2,%3};"
        : "+f"(d[0]), "+f"(d[1]), "+f"(d[2]), "+f"(d[3])
        : "r"(a[0]), "r"(a[1]), "r"(a[2]), "r"(a[3]), "r"(b0), "r"(b1));
}
__device__ __forceinline__ float gelu_exact(float x) {
    return 0.5f * x * (1.0f + erff(x * 0.7071067811865476f));
}

// ---------------- weight transpose -> fp16 (z = layer) ----------------
__global__ __launch_bounds__(256) void wsplit_kernel(
        const float* __restrict__ W, __half* __restrict__ T, int K, int N,
        size_t dstStride) {
    const float* Wl = W + (size_t)blockIdx.z * K * N;
    __half* Tl = T + (size_t)blockIdx.z * dstStride;
    __shared__ float t[32][33];
    const int n0 = blockIdx.x * 32, k0 = blockIdx.y * 32;
    const int tx = threadIdx.x & 31, ty = threadIdx.x >> 5;
    #pragma unroll
    for (int i = 0; i < 4; i++) {
        int k = ty + i * 8;
        t[k][tx] = Wl[(size_t)(k0 + k) * N + n0 + tx];
    }
    __syncthreads();
    #pragma unroll
    for (int i = 0; i < 4; i++) {
        int n = ty + i * 8;
        Tl[(size_t)(n0 + n) * K + k0 + tx] = __float2half_rn(t[tx][n]);
    }
}

// ---------------- LayerNorm (+gelu), warp-per-row, fp16 out ----------------
__global__ __launch_bounds__(256) void ln_kernel(
        const float* __restrict__ in, __half* __restrict__ oh,
        const float* __restrict__ gamma, const float* __restrict__ beta,
        int W, float eps, int do_gelu, int rows) {
    const int w = threadIdx.x >> 5, lane = threadIdx.x & 31;
    const int row = blockIdx.x * 8 + w;
    if (row >= rows) return;
    const float2* p = (const float2*)(in + (size_t)row * W);
    const int W2 = W >> 1;
    float s = 0.f, ss = 0.f;
    for (int j = lane; j < W2; j += 32) {
        float2 v = p[j];
        s += v.x + v.y;
        ss += v.x * v.x + v.y * v.y;
    }
    #pragma unroll
    for (int off = 16; off; off >>= 1) {
        s  += __shfl_xor_sync(0xffffffffu, s, off);
        ss += __shfl_xor_sync(0xffffffffu, ss, off);
    }
    const float mean = s / (float)W;
    const float var  = ss / (float)W - mean * mean;
    const float inv  = rsqrtf(var + eps);
    const float2* g2 = (const float2*)gamma;
    const float2* b2 = (const float2*)beta;
    __half2* o2 = (__half2*)(oh + (size_t)row * W);
    for (int j = lane; j < W2; j += 32) {
        float2 v = p[j], g = g2[j], b = b2[j];
        float v0 = (v.x - mean) * inv * g.x + b.x;
        float v1 = (v.y - mean) * inv * g.y + b.y;
        if (do_gelu) { v0 = gelu_exact(v0); v1 = gelu_exact(v1); }
        __half2 hp; hp.x = __float2half_rn(v0); hp.y = __float2half_rn(v1);
        o2[j] = hp;
    }
}

// ---------------- depthwise 2x2/s2 conv, fp16 in -> fp16 out ----------------
__global__ void dwconv_kernel(const __half* __restrict__ y,
                              const float* __restrict__ w4, const float* __restrict__ bias,
                              __half* __restrict__ oh) {
    const int m = blockIdx.x, b = blockIdx.y;
    const int h7 = m / 7, w7 = m % 7;
    const int p00 = (h7 * 2) * HW + w7 * 2;
    const __half* yb = y + (size_t)b * NTOK * CDIM;
    const size_t ob = ((size_t)b * MTOK + m) * CDIM;
    for (int c = threadIdx.x; c < CDIM; c += blockDim.x) {
        float acc = __half2float(yb[(size_t)(p00         ) * CDIM + c]) * w4[c * 4 + 0]
                  + __half2float(yb[(size_t)(p00 + 1     ) * CDIM + c]) * w4[c * 4 + 1]
                  + __half2float(yb[(size_t)(p00 + HW    ) * CDIM + c]) * w4[c * 4 + 2]
                  + __half2float(yb[(size_t)(p00 + HW + 1) * CDIM + c]) * w4[c * 4 + 3]
                  + bias[c];
        oh[ob + c] = __float2half_rn(acc);
    }
}

// ---------------------------------------------------------------------------
// fp16 GEMM on HMMA: C = A[M,K] @ B[N,K]^T
// CTA tile BM x BN, warp grid NM x NN, each warp computes (16*MT) x (BN/NN).
// BK=64, 3-stage cp.async pipeline, RSTRIDE=144 (conflict-free ldmatrix).
// MT=4 (64-row warp tiles) cuts smem read traffic 96->64KB/chunk on 128x128.
// EPI: 1 +bias fp32, 2 +bias+gelu fp16, 3 +bias+resid fp32, 4 plain fp16,
//      5 fp16 split kv (cols < CNEW -> Ch stride CNEW, else Ch2 stride CDIM)
// ---------------------------------------------------------------------------
#define RSTRIDE 144

template <int BM, int BN, int NM, int NN, int MT, int EPI>
__global__ __launch_bounds__(32*NM*NN, 1024/(32*NM*NN*MT)) void tcmm_kernel(
        const __half* __restrict__ A, const __half* __restrict__ B,
        const float* __restrict__ bias, const float* __restrict__ resid,
        float* __restrict__ Cf, __half* __restrict__ Ch, __half* __restrict__ Ch2,
        int M, int N, int K) {
    constexpr int NT   = 32 * NM * NN;
    constexpr int SS   = (BM + BN) * RSTRIDE;    // stage bytes
    constexpr int WN   = BN / NN;
    constexpr int WN8  = WN / 8;
    constexpr int WN16 = WN / 16;
    constexpr int WROWS = 16 * MT;
    static_assert(BM == NM * WROWS, "warp rows x NM must equal BM");
    extern __shared__ char smem[];
    const int tid = threadIdx.x, lane = tid & 31, wid = tid >> 5;
    const int wn = wid % NN, wm = wid / NN;
    const int row0 = blockIdx.y * BM, col0 = blockIdx.x * BN;
    const uint32_t tiles = (smem_u32(smem) + 1023) & ~1023u;

    float acc[MT][WN8][4];
    #pragma unroll
    for (int a = 0; a < MT; a++)
        #pragma unroll
        for (int b = 0; b < WN8; b++)
            #pragma unroll
            for (int c = 0; c < 4; c++) acc[a][b][c] = 0.f;

    const int NC = K >> 6;   // BK = 64

    auto load_chunk = [&](int stage, int k0) {
        uint32_t sd = tiles + stage * SS;
        #pragma unroll
        for (int i = 0; i < BM * 8 / NT; i++) {      // A: BM rows x 128B
            int idx = tid + i * NT;
            int row = idx >> 3, cc = idx & 7;
            int grow = row0 + row; if (grow > M - 1) grow = M - 1;
            cp16(sd + row * RSTRIDE + cc * 16, A + (size_t)grow * K + k0 + cc * 8);
        }
        #pragma unroll
        for (int i = 0; i < BN * 8 / NT; i++) {      // B: BN rows x 128B
            int idx = tid + i * NT;
            int row = idx >> 3, cc = idx & 7;
            cp16(sd + BM * RSTRIDE + row * RSTRIDE + cc * 16,
                 B + (size_t)(col0 + row) * K + k0 + cc * 8);
        }
    };

    load_chunk(0, 0);  cp_commit();
    load_chunk(1, 64); cp_commit();

    for (int c = 0; c < NC; c++) {
        if (c + 2 < NC) cp_wait<1>(); else cp_wait<0>();
        __syncthreads();
        if (c + 2 < NC) { load_chunk((c + 2) % 3, (c + 2) * 64); cp_commit(); }

        const uint32_t sA = tiles + (c % 3) * SS;
        const uint32_t sB = sA + BM * RSTRIDE;
        #pragma unroll
        for (int ks = 0; ks < 4; ks++) {
            uint32_t ah[MT][4];
            #pragma unroll
            for (int mt = 0; mt < MT; mt++) {
                uint32_t r = sA + (wm * WROWS + mt * 16 + (lane & 15)) * RSTRIDE
                           + (2 * ks + (lane >> 4)) * 16;
                ldsm_x4(ah[mt], r);
            }
            uint32_t bh[WN16][4];
            #pragma unroll
            for (int g = 0; g < WN16; g++) {
                int rrow = wn * WN + g * 16 + (lane & 7) + ((lane >> 4) << 3);
                uint32_t r = sB + rrow * RSTRIDE + (2 * ks + ((lane >> 3) & 1)) * 16;
                ldsm_x4(bh[g], r);
            }
            #pragma unroll
            for (int mt = 0; mt < MT; mt++)
                #pragma unroll
                for (int g = 0; g < WN16; g++) {
                    mma16816(acc[mt][2*g],   ah[mt], bh[g][0], bh[g][1]);
                    mma16816(acc[mt][2*g+1], ah[mt], bh[g][2], bh[g][3]);
                }
        }
    }

    // epilogue
    const int er = lane >> 2, ec = (lane & 3) * 2;
    #pragma unroll
    for (int mt = 0; mt < MT; mt++) {
        #pragma unroll
        for (int g = 0; g < WN8; g++) {
            const int gn = col0 + wn * WN + g * 8 + ec;
            #pragma unroll
            for (int hrow = 0; hrow < 2; hrow++) {
                const int gm = row0 + wm * WROWS + mt * 16 + er + hrow * 8;
                if (gm >= M) continue;
                float v0 = acc[mt][g][2 * hrow];
                float v1 = acc[mt][g][2 * hrow + 1];
                if constexpr (EPI == 1 || EPI == 2 || EPI == 3) {
                    v0 += bias[gn]; v1 += bias[gn + 1];
                }
                if constexpr (EPI == 2) { v0 = gelu_exact(v0); v1 = gelu_exact(v1); }
                if constexpr (EPI == 2 || EPI == 4) {
                    __half2 hp; hp.x = __float2half_rn(v0); hp.y = __float2half_rn(v1);
                    *(__half2*)(Ch + (size_t)gm * N + gn) = hp;
                } else if constexpr (EPI == 5) {
                    __half2 hp; hp.x = __float2half_rn(v0); hp.y = __float2half_rn(v1);
                    if (gn < CNEW) *(__half2*)(Ch  + (size_t)gm * CNEW + gn) = hp;
                    else           *(__half2*)(Ch2 + (size_t)gm * CDIM + gn - CNEW) = hp;
                } else {
                    const size_t base = (size_t)gm * N + gn;
                    if constexpr (EPI == 3) {
                        float2 rs = *(const float2*)(resid + base);
                        v0 += rs.x; v1 += rs.y;
                    }
                    float2 o; o.x = v0; o.y = v1;
                    *(float2*)(Cf + base) = o;
                }
            }
        }
    }
}

// ---------------- attention: fp16 in, fp32 math, fp16 out, 256 thr ----------------
__global__ __launch_bounds__(256) void attn_kernel(
        const __half* __restrict__ q, const __half* __restrict__ k,
        const __half* __restrict__ v, __half* __restrict__ oh) {
    const int b = blockIdx.x / NHEAD;
    const int hh = blockIdx.x % NHEAD;
    __shared__ float ks[MTOK][HDK + 1];
    __shared__ float vs[MTOK][HD + 1];
    __shared__ float qs[8][HDK];
    __shared__ float ps[8][MTOK];
    const int tid = threadIdx.x, w = tid >> 5, lane = tid & 31;
    const __half* kb = k + (size_t)b * MTOK * CNEW + hh * HDK;
    const __half* vb = v + (size_t)b * MTOK * CDIM + hh * HD;
    for (int i = tid; i < MTOK * HDK; i += 256) {
        int m = i / HDK, d = i % HDK;
        ks[m][d] = __half2float(kb[(size_t)m * CNEW + d]);
    }
    for (int i = tid; i < MTOK * HD; i += 256) {
        int m = i / HD, d = i % HD;
        vs[m][d] = __half2float(vb[(size_t)m * CDIM + d]);
    }
    __syncthreads();
    const float scale = rsqrtf(80.0f);
    for (int n = w; n < NTOK; n += 8) {
        const __half* qp = q + ((size_t)(b * NTOK + n)) * CNEW + hh * HDK;
        for (int i = lane; i < HDK; i += 32) qs[w][i] = __half2float(qp[i]);
        __syncwarp();
        float s0 = 0.f, s1 = 0.f;
        #pragma unroll
        for (int d = 0; d < HDK; d++) {
            float qv = qs[w][d];
            s0 = fmaf(qv, ks[lane][d], s0);
            if (lane < MTOK - 32) s1 = fmaf(qv, ks[lane + 32][d], s1);
        }
        s0 *= scale; s1 *= scale;
        float mx = fmaxf(s0, (lane < MTOK - 32) ? s1 : -1e30f);
        #pragma unroll
        for (int off = 16; off; off >>= 1) mx = fmaxf(mx, __shfl_xor_sync(0xffffffffu, mx, off));
        float e0 = expf(s0 - mx);
        float e1 = (lane < MTOK - 32) ? expf(s1 - mx) : 0.f;
        float sm = e0 + e1;
        #pragma unroll
        for (int off = 16; off; off >>= 1) sm += __shfl_xor_sync(0xffffffffu, sm, off);
        float inv = 1.f / sm;
        ps[w][lane] = e0 * inv;
        if (lane < MTOK - 32) ps[w][lane + 32] = e1 * inv;
        __syncwarp();
        float a0 = 0.f, a1 = 0.f;
        #pragma unroll
        for (int m = 0; m < MTOK; m++) {
            float p = ps[w][m];
            a0 = fmaf(p, vs[m][lane], a0);
            a1 = fmaf(p, vs[m][lane + 32], a1);
        }
        size_t o0 = ((size_t)(b * NTOK + n)) * CDIM + hh * HD + lane;
        oh[o0]      = __float2half_rn(a0);
        oh[o0 + 32] = __float2half_rn(a1);
        __syncwarp();
    }
}

// ---------------- host ----------------
static inline int cdiv(int a, int b) { return (a + b - 1) / b; }
#define SMEM_OF(BM, BN) (1024 + 3 * ((BM + BN) * RSTRIDE))

extern "C" void kernel_launch(void* const* d_in, const int* in_sizes, int n_in,
                              void* d_out, int out_size) {
    const float* x_in   = (const float*)d_in[0];
    const float* q_w    = (const float*)d_in[1];
    const float* dw_w   = (const float*)d_in[2];
    const float* dw_b   = (const float*)d_in[3];
    const float* pw_w   = (const float*)d_in[4];
    const float* pw_b   = (const float*)d_in[5];
    const float* lnr_g  = (const float*)d_in[6];
    const float* lnr_b  = (const float*)d_in[7];
    const float* k_w    = (const float*)d_in[8];
    const float* v_w    = (const float*)d_in[9];
    const float* proj_w = (const float*)d_in[10];
    const float* proj_b = (const float*)d_in[11];
    const float* ln1_g  = (const float*)d_in[12];
    const float* ln1_b  = (const float*)d_in[13];
    const float* ln2_g  = (const float*)d_in[14];
    const float* ln2_b  = (const float*)d_in[15];
    const float* fc1_w  = (const float*)d_in[16];
    const float* fc1_b  = (const float*)d_in[17];
    const float* fc2_w  = (const float*)d_in[18];
    const float* fc2_b  = (const float*)d_in[19];

    float* xcur = (float*)d_out;

    float* p_r0;
    __half *p_yh, *p_rch, *p_rh, *p_qh, *p_kh, *p_vh, *p_oh, *p_hh;
    __half *wq, *wpw, *wkv, *wp, *w1, *w2;
    cudaGetSymbolAddress((void**)&p_r0, g_r0);
    cudaGetSymbolAddress((void**)&p_yh, g_yh);   cudaGetSymbolAddress((void**)&p_rch, g_rch);
    cudaGetSymbolAddress((void**)&p_rh, g_rh);
    cudaGetSymbolAddress((void**)&p_qh, g_qh);   cudaGetSymbolAddress((void**)&p_kh, g_kh);
    cudaGetSymbolAddress((void**)&p_vh, g_vh);
    cudaGetSymbolAddress((void**)&p_oh, g_oh);   cudaGetSymbolAddress((void**)&p_hh, g_hh);
    cudaGetSymbolAddress((void**)&wq, g_wq);     cudaGetSymbolAddress((void**)&wpw, g_wpw);
    cudaGetSymbolAddress((void**)&wkv, g_wkv);
    cudaGetSymbolAddress((void**)&wp, g_wp);     cudaGetSymbolAddress((void**)&w1, g_w1);
    cudaGetSymbolAddress((void**)&w2, g_w2);

    cudaFuncSetAttribute(tcmm_kernel<64,64,2,2,2,1>,    cudaFuncAttributeMaxDynamicSharedMemorySize, SMEM_OF(64,64));
    cudaFuncSetAttribute(tcmm_kernel<64,64,2,2,2,5>,    cudaFuncAttributeMaxDynamicSharedMemorySize, SMEM_OF(64,64));
    cudaFuncSetAttribute(tcmm_kernel<128,64,2,2,4,4>,   cudaFuncAttributeMaxDynamicSharedMemorySize, SMEM_OF(128,64));
    cudaFuncSetAttribute(tcmm_kernel<128,128,2,2,4,2>,  cudaFuncAttributeMaxDynamicSharedMemorySize, SMEM_OF(128,128));
    cudaFuncSetAttribute(tcmm_kernel<128,128,2,2,4,3>,  cudaFuncAttributeMaxDynamicSharedMemorySize, SMEM_OF(128,128));

    // side stream + fork/join events (host-side resources only)
    cudaStream_t s1;
    cudaStreamCreateWithFlags(&s1, cudaStreamNonBlocking);
    cudaEvent_t evFork, evJoin;
    cudaEventCreateWithFlags(&evFork, cudaEventDisableTiming);
    cudaEventCreateWithFlags(&evJoin, cudaEventDisableTiming);

    // weight transpose, all layers batched via grid.z
    wsplit_kernel<<<dim3(CNEW/32,   CDIM/32,   LAYERS), 256>>>(q_w,    wq,  CDIM,   CNEW, (size_t)CDIM*CNEW);
    wsplit_kernel<<<dim3(CNEW/32,   CDIM/32,   LAYERS), 256>>>(pw_w,   wpw, CDIM,   CNEW, (size_t)CDIM*CNEW);
    wsplit_kernel<<<dim3(CNEW/32,   CNEW/32,   LAYERS), 256>>>(k_w,    wkv, CNEW,   CNEW, (size_t)NKV*CNEW);
    wsplit_kernel<<<dim3(CDIM/32,   CNEW/32,   LAYERS), 256>>>(v_w,    wkv + (size_t)CNEW*CNEW,
                                                               CNEW,   CDIM, (size_t)NKV*CNEW);
    wsplit_kernel<<<dim3(CDIM/32,   CDIM/32,   LAYERS), 256>>>(proj_w, wp,  CDIM,   CDIM, (size_t)CDIM*CDIM);
    wsplit_kernel<<<dim3(HIDDIM/32, CDIM/32,   LAYERS), 256>>>(fc1_w,  w1,  CDIM,   HIDDIM, (size_t)CDIM*HIDDIM);
    wsplit_kernel<<<dim3(CDIM/32,   HIDDIM/32, LAYERS), 256>>>(fc2_w,  w2,  HIDDIM, CDIM, (size_t)HIDDIM*CDIM);

    for (int l = 0; l < LAYERS; l++) {
        const float* xin = (l == 0) ? x_in : xcur;   // layer 0 reads harness input
        // y = LN1(x) -> fp16
        ln_kernel<<<cdiv(ROWS_X,8), 256>>>(xin, p_yh,
            ln1_g + l*CDIM, ln1_b + l*CDIM, CDIM, 1e-6f, 0, ROWS_X);

        // ---- fork: reduction branch on s1, q GEMM on main stream ----
        cudaEventRecord(evFork, 0);
        cudaStreamWaitEvent(s1, evFork, 0);

        dwconv_kernel<<<dim3(MTOK, BATCH), 256, 0, s1>>>(p_yh, dw_w + (size_t)l*CDIM*4,
                                                         dw_b + l*CDIM, p_rch);
        // r0 = rconv @ pw + b   (3136 x 960, K=768)
        tcmm_kernel<64,64,2,2,2,1><<<dim3(CNEW/64, ROWS_R/64), 128, SMEM_OF(64,64), s1>>>(
            p_rch, wpw + (size_t)l*CNEW*CDIM,
            pw_b + l*CNEW, nullptr, p_r0, nullptr, nullptr, ROWS_R, CNEW, CDIM);
        // r = gelu(LN(r0)) -> fp16
        ln_kernel<<<cdiv(ROWS_R,8), 256, 0, s1>>>(p_r0, p_rh,
            lnr_g + l*CNEW, lnr_b + l*CNEW, CNEW, 1e-5f, 1, ROWS_R);
        // k|v = r @ [k_w; v_w] -> fp16 split   (3136 x 1728, K=960)
        tcmm_kernel<64,64,2,2,2,5><<<dim3(NKV/64, ROWS_R/64), 128, SMEM_OF(64,64), s1>>>(
            p_rh, wkv + (size_t)l*NKV*CNEW,
            nullptr, nullptr, nullptr, p_kh, p_vh, ROWS_R, NKV, CNEW);
        cudaEventRecord(evJoin, s1);

        // q = y @ q_w -> fp16   (12544 x 960, K=768)  [concurrent with s1 chain]
        tcmm_kernel<128,64,2,2,4,4><<<dim3(CNEW/64, ROWS_X/128), 128, SMEM_OF(128,64)>>>(
            p_yh, wq + (size_t)l*CNEW*CDIM,
            nullptr, nullptr, nullptr, p_qh, nullptr, ROWS_X, CNEW, CDIM);

        // ---- join ----
        cudaStreamWaitEvent(0, evJoin, 0);

        attn_kernel<<<BATCH*NHEAD, 256>>>(p_qh, p_kh, p_vh, p_oh);
        // x(out) = resid + o @ proj + b   (12544 x 768, K=768)
        tcmm_kernel<128,128,2,2,4,3><<<dim3(CDIM/128, ROWS_X/128), 128, SMEM_OF(128,128)>>>(
            p_oh, wp + (size_t)l*CDIM*CDIM,
            proj_b + l*CDIM, xin, xcur, nullptr, nullptr, ROWS_X, CDIM, CDIM);
        // z = LN2(x) -> fp16
        ln_kernel<<<cdiv(ROWS_X,8), 256>>>(xcur, p_yh,
            ln2_g + l*CDIM, ln2_b + l*CDIM, CDIM, 1e-6f, 0, ROWS_X);
        // h = gelu(z @ fc1 + b) -> fp16  (12544 x 3072, K=768)
        tcmm_kernel<128,128,2,2,4,2><<<dim3(HIDDIM/128, ROWS_X/128), 128, SMEM_OF(128,128)>>>(
            p_yh, w1 + (size_t)l*HIDDIM*CDIM,
            fc1_b + l*HIDDIM, nullptr, nullptr, p_hh, nullptr, ROWS_X, HIDDIM, CDIM);
        // x += h @ fc2 + b      (12544 x 768, K=3072)
        tcmm_kernel<128,128,2,2,4,3><<<dim3(CDIM/128, ROWS_X/128), 128, SMEM_OF(128,128)>>>(
            p_hh, w2 + (size_t)l*CDIM*HIDDIM,
            fc2_b + l*CDIM, xcur, xcur, nullptr, nullptr, ROWS_X, CDIM, HIDDIM);
    }
}

// round 15
// speedup vs baseline: 1.0396x; 1.0396x over previous
#include <cuda_runtime.h>
#include <cuda_fp16.h>
#include <math.h>
#include <stdint.h>

#define LAYERS 4
#define BATCH  64
#define NTOK   196
#define CDIM   768
#define CNEW   960
#define HIDDIM 3072
#define NHEAD  12
#define HD     64
#define HDK    80
#define MTOK   49
#define HW     14
#define ROWS_X (BATCH * NTOK)   // 12544
#define ROWS_R (BATCH * MTOK)   // 3136
#define NKV    (CNEW + CDIM)    // 1728

// ---------------- scratch ----------------
__device__ float g_r0[ROWS_R * CNEW];
__device__ __align__(16) __half g_yh[ROWS_X * CDIM];
__device__ __align__(16) __half g_rch[ROWS_R * CDIM];
__device__ __align__(16) __half g_rh[ROWS_R * CNEW];
__device__ __align__(16) __half g_qh[ROWS_X * CNEW];
__device__ __align__(16) __half g_kh[ROWS_R * CNEW];
__device__ __align__(16) __half g_vh[ROWS_R * CDIM];
__device__ __align__(16) __half g_oh[ROWS_X * CDIM];
__device__ __align__(16) __half g_hh[ROWS_X * HIDDIM];

// transposed weights, [N][K] K-major fp16
__device__ __align__(16) __half g_wq [LAYERS*CNEW*CDIM];
__device__ __align__(16) __half g_wpw[LAYERS*CNEW*CDIM];
__device__ __align__(16) __half g_wkv[LAYERS*NKV*CNEW];
__device__ __align__(16) __half g_wp [LAYERS*CDIM*CDIM];
__device__ __align__(16) __half g_w1 [LAYERS*HIDDIM*CDIM];
__device__ __align__(16) __half g_w2 [LAYERS*CDIM*HIDDIM];

// ---------------- helpers ----------------
__device__ __forceinline__ uint32_t smem_u32(const void* p) {
    uint32_t a;
    asm("{ .reg .u64 t; cvta.to.shared.u64 t, %1; cvt.u32.u64 %0, t; }" : "=r"(a) : "l"(p));
    return a;
}
__device__ __forceinline__ void cp16(uint32_t dst, const void* src) {
    asm volatile("cp.async.cg.shared.global [%0], [%1], 16;" :: "r"(dst), "l"(src));
}
__device__ __forceinline__ void cp_commit() { asm volatile("cp.async.commit_group;" ::: "memory"); }
template <int N> __device__ __forceinline__ void cp_wait() {
    asm volatile("cp.async.wait_group %0;" :: "n"(N) : "memory");
}
__device__ __forceinline__ void ldsm_x4(uint32_t (&r)[4], uint32_t addr) {
    asm volatile("ldmatrix.sync.aligned.m8n8.x4.shared.b16 {%0,%1,%2,%3}, [%4];"
        : "=r"(r[0]), "=r"(r[1]), "=r"(r[2]), "=r"(r[3]) : "r"(addr));
}
__device__ __forceinline__ void mma16816(float (&d)[4], const uint32_t (&a)[4],
                                         uint32_t b0, uint32_t b1) {
    asm volatile("mma.sync.aligned.m16n8k16.row.col.f32.f16.f16.f32 "
        "{%0,%1,%2,%3}, {%4,%5,%6,%7}, {%8,%9}, {%0,%1,%2,%3};"
        : "+f"(d[0]), "+f"(d[1]), "+f"(d[2]), "+f"(d[3])
        : "r"(a[0]), "r"(a[1]), "r"(a[2]), "r"(a[3]), "r"(b0), "r"(b1));
}
__device__ __forceinline__ float gelu_exact(float x) {
    return 0.5f * x * (1.0f + erff(x * 0.7071067811865476f));
}

// ---------------- weight transpose -> fp16 (z = layer) ----------------
__global__ __launch_bounds__(256) void wsplit_kernel(
        const float* __restrict__ W, __half* __restrict__ T, int K, int N,
        size_t dstStride) {
    const float* Wl = W + (size_t)blockIdx.z * K * N;
    __half* Tl = T + (size_t)blockIdx.z * dstStride;
    __shared__ float t[32][33];
    const int n0 = blockIdx.x * 32, k0 = blockIdx.y * 32;
    const int tx = threadIdx.x & 31, ty = threadIdx.x >> 5;
    #pragma unroll
    for (int i = 0; i < 4; i++) {
        int k = ty + i * 8;
        t[k][tx] = Wl[(size_t)(k0 + k) * N + n0 + tx];
    }
    __syncthreads();
    #pragma unroll
    for (int i = 0; i < 4; i++) {
        int n = ty + i * 8;
        Tl[(size_t)(n0 + n) * K + k0 + tx] = __float2half_rn(t[tx][n]);
    }
}

// ---------------- LayerNorm (+gelu), warp-per-row, float4, fp16 out ----------------
__global__ __launch_bounds__(256) void ln_kernel(
        const float* __restrict__ in, __half* __restrict__ oh,
        const float* __restrict__ gamma, const float* __restrict__ beta,
        int W, float eps, int do_gelu, int rows) {
    const int w = threadIdx.x >> 5, lane = threadIdx.x & 31;
    const int row = blockIdx.x * 8 + w;
    if (row >= rows) return;
    const float4* p = (const float4*)(in + (size_t)row * W);
    const int W4 = W >> 2;
    float s = 0.f, ss = 0.f;
    for (int j = lane; j < W4; j += 32) {
        float4 v = p[j];
        s  += (v.x + v.y) + (v.z + v.w);
        ss += (v.x * v.x + v.y * v.y) + (v.z * v.z + v.w * v.w);
    }
    #pragma unroll
    for (int off = 16; off; off >>= 1) {
        s  += __shfl_xor_sync(0xffffffffu, s, off);
        ss += __shfl_xor_sync(0xffffffffu, ss, off);
    }
    const float mean = s / (float)W;
    const float var  = ss / (float)W - mean * mean;
    const float inv  = rsqrtf(var + eps);
    const float4* g4 = (const float4*)gamma;
    const float4* b4 = (const float4*)beta;
    uint2* o4 = (uint2*)(oh + (size_t)row * W);
    for (int j = lane; j < W4; j += 32) {
        float4 v = p[j], g = g4[j], b = b4[j];
        float v0 = (v.x - mean) * inv * g.x + b.x;
        float v1 = (v.y - mean) * inv * g.y + b.y;
        float v2 = (v.z - mean) * inv * g.z + b.z;
        float v3 = (v.w - mean) * inv * g.w + b.w;
        if (do_gelu) {
            v0 = gelu_exact(v0); v1 = gelu_exact(v1);
            v2 = gelu_exact(v2); v3 = gelu_exact(v3);
        }
        __half2 lo; lo.x = __float2half_rn(v0); lo.y = __float2half_rn(v1);
        __half2 hi; hi.x = __float2half_rn(v2); hi.y = __float2half_rn(v3);
        uint2 o; o.x = *(uint32_t*)&lo; o.y = *(uint32_t*)&hi;
        o4[j] = o;
    }
}

// ---------------- depthwise 2x2/s2 conv, fp16 in -> fp16 out ----------------
__global__ void dwconv_kernel(const __half* __restrict__ y,
                              const float* __restrict__ w4, const float* __restrict__ bias,
                              __half* __restrict__ oh) {
    const int m = blockIdx.x, b = blockIdx.y;
    const int h7 = m / 7, w7 = m % 7;
    const int p00 = (h7 * 2) * HW + w7 * 2;
    const __half* yb = y + (size_t)b * NTOK * CDIM;
    const size_t ob = ((size_t)b * MTOK + m) * CDIM;
    for (int c = threadIdx.x; c < CDIM; c += blockDim.x) {
        float acc = __half2float(yb[(size_t)(p00         ) * CDIM + c]) * w4[c * 4 + 0]
                  + __half2float(yb[(size_t)(p00 + 1     ) * CDIM + c]) * w4[c * 4 + 1]
                  + __half2float(yb[(size_t)(p00 + HW    ) * CDIM + c]) * w4[c * 4 + 2]
                  + __half2float(yb[(size_t)(p00 + HW + 1) * CDIM + c]) * w4[c * 4 + 3]
                  + bias[c];
        oh[ob + c] = __float2half_rn(acc);
    }
}

// ---------------------------------------------------------------------------
// fp16 GEMM on HMMA: C = A[M,K] @ B[N,K]^T   (R12 shapes: known-good)
// CTA tile BM x BN, warp grid NM x NN, BK=64, 3-stage cp.async pipeline,
// RSTRIDE=144 (conflict-free ldmatrix).
// EPI: 1 +bias fp32, 2 +bias+gelu fp16, 3 +bias+resid fp32, 4 plain fp16,
//      5 fp16 split kv (cols < CNEW -> Ch stride CNEW, else Ch2 stride CDIM)
// ---------------------------------------------------------------------------
#define RSTRIDE 144

template <int BM, int BN, int NM, int NN, int EPI>
__global__ __launch_bounds__(32*NM*NN, 512/(32*NM*NN)) void tcmm_kernel(
        const __half* __restrict__ A, const __half* __restrict__ B,
        const float* __restrict__ bias, const float* __restrict__ resid,
        float* __restrict__ Cf, __half* __restrict__ Ch, __half* __restrict__ Ch2,
        int M, int N, int K) {
    constexpr int NT   = 32 * NM * NN;
    constexpr int SS   = (BM + BN) * RSTRIDE;
    constexpr int WN   = BN / NN;
    constexpr int WN8  = WN / 8;
    constexpr int WN16 = WN / 16;
    static_assert(BM / NM == 32, "each warp covers 32 rows (2 mt tiles)");
    extern __shared__ char smem[];
    const int tid = threadIdx.x, lane = tid & 31, wid = tid >> 5;
    const int wn = wid % NN, wm = wid / NN;
    const int row0 = blockIdx.y * BM, col0 = blockIdx.x * BN;
    const uint32_t tiles = (smem_u32(smem) + 1023) & ~1023u;

    float acc[2][WN8][4];
    #pragma unroll
    for (int a = 0; a < 2; a++)
        #pragma unroll
        for (int b = 0; b < WN8; b++)
            #pragma unroll
            for (int c = 0; c < 4; c++) acc[a][b][c] = 0.f;

    const int NC = K >> 6;   // BK = 64

    auto load_chunk = [&](int stage, int k0) {
        uint32_t sd = tiles + stage * SS;
        #pragma unroll
        for (int i = 0; i < BM * 8 / NT; i++) {      // A: BM rows x 128B
            int idx = tid + i * NT;
            int row = idx >> 3, cc = idx & 7;
            int grow = row0 + row; if (grow > M - 1) grow = M - 1;
            cp16(sd + row * RSTRIDE + cc * 16, A + (size_t)grow * K + k0 + cc * 8);
        }
        #pragma unroll
        for (int i = 0; i < BN * 8 / NT; i++) {      // B: BN rows x 128B
            int idx = tid + i * NT;
            int row = idx >> 3, cc = idx & 7;
            cp16(sd + BM * RSTRIDE + row * RSTRIDE + cc * 16,
                 B + (size_t)(col0 + row) * K + k0 + cc * 8);
        }
    };

    load_chunk(0, 0);  cp_commit();
    load_chunk(1, 64); cp_commit();

    for (int c = 0; c < NC; c++) {
        if (c + 2 < NC) cp_wait<1>(); else cp_wait<0>();
        __syncthreads();
        if (c + 2 < NC) { load_chunk((c + 2) % 3, (c + 2) * 64); cp_commit(); }

        const uint32_t sA = tiles + (c % 3) * SS;
        const uint32_t sB = sA + BM * RSTRIDE;
        #pragma unroll
        for (int ks = 0; ks < 4; ks++) {
            uint32_t ah[2][4];
            #pragma unroll
            for (int mt = 0; mt < 2; mt++) {
                uint32_t r = sA + (wm * 32 + mt * 16 + (lane & 15)) * RSTRIDE
                           + (2 * ks + (lane >> 4)) * 16;
                ldsm_x4(ah[mt], r);
            }
            uint32_t bh[WN16][4];
            #pragma unroll
            for (int g = 0; g < WN16; g++) {
                int rrow = wn * WN + g * 16 + (lane & 7) + ((lane >> 4) << 3);
                uint32_t r = sB + rrow * RSTRIDE + (2 * ks + ((lane >> 3) & 1)) * 16;
                ldsm_x4(bh[g], r);
            }
            #pragma unroll
            for (int mt = 0; mt < 2; mt++)
                #pragma unroll
                for (int g = 0; g < WN16; g++) {
                    mma16816(acc[mt][2*g],   ah[mt], bh[g][0], bh[g][1]);
                    mma16816(acc[mt][2*g+1], ah[mt], bh[g][2], bh[g][3]);
                }
        }
    }

    // epilogue
    const int er = lane >> 2, ec = (lane & 3) * 2;
    #pragma unroll
    for (int mt = 0; mt < 2; mt++) {
        #pragma unroll
        for (int g = 0; g < WN8; g++) {
            const int gn = col0 + wn * WN + g * 8 + ec;
            #pragma unroll
            for (int hrow = 0; hrow < 2; hrow++) {
                const int gm = row0 + wm * 32 + mt * 16 + er + hrow * 8;
                if (gm >= M) continue;
                float v0 = acc[mt][g][2 * hrow];
                float v1 = acc[mt][g][2 * hrow + 1];
                if constexpr (EPI == 1 || EPI == 2 || EPI == 3) {
                    v0 += bias[gn]; v1 += bias[gn + 1];
                }
                if constexpr (EPI == 2) { v0 = gelu_exact(v0); v1 = gelu_exact(v1); }
                if constexpr (EPI == 2 || EPI == 4) {
                    __half2 hp; hp.x = __float2half_rn(v0); hp.y = __float2half_rn(v1);
                    *(__half2*)(Ch + (size_t)gm * N + gn) = hp;
                } else if constexpr (EPI == 5) {
                    __half2 hp; hp.x = __float2half_rn(v0); hp.y = __float2half_rn(v1);
                    if (gn < CNEW) *(__half2*)(Ch  + (size_t)gm * CNEW + gn) = hp;
                    else           *(__half2*)(Ch2 + (size_t)gm * CDIM + gn - CNEW) = hp;
                } else {
                    const size_t base = (size_t)gm * N + gn;
                    if constexpr (EPI == 3) {
                        float2 rs = *(const float2*)(resid + base);
                        v0 += rs.x; v1 += rs.y;
                    }
                    float2 o; o.x = v0; o.y = v1;
                    *(float2*)(Cf + base) = o;
                }
            }
        }
    }
}

// ---------------- attention: fp16 in, fp32 math, fp16 out, 256 thr ----------------
__global__ __launch_bounds__(256) void attn_kernel(
        const __half* __restrict__ q, const __half* __restrict__ k,
        const __half* __restrict__ v, __half* __restrict__ oh) {
    const int b = blockIdx.x / NHEAD;
    const int hh = blockIdx.x % NHEAD;
    __shared__ float ks[MTOK][HDK + 1];
    __shared__ float vs[MTOK][HD + 1];
    __shared__ float qs[8][HDK];
    __shared__ float ps[8][MTOK];
    const int tid = threadIdx.x, w = tid >> 5, lane = tid & 31;
    const __half* kb = k + (size_t)b * MTOK * CNEW + hh * HDK;
    const __half* vb = v + (size_t)b * MTOK * CDIM + hh * HD;
    for (int i = tid; i < MTOK * HDK; i += 256) {
        int m = i / HDK, d = i % HDK;
        ks[m][d] = __half2float(kb[(size_t)m * CNEW + d]);
    }
    for (int i = tid; i < MTOK * HD; i += 256) {
        int m = i / HD, d = i % HD;
        vs[m][d] = __half2float(vb[(size_t)m * CDIM + d]);
    }
    __syncthreads();
    const float scale = rsqrtf(80.0f);
    for (int n = w; n < NTOK; n += 8) {
        const __half* qp = q + ((size_t)(b * NTOK + n)) * CNEW + hh * HDK;
        for (int i = lane; i < HDK; i += 32) qs[w][i] = __half2float(qp[i]);
        __syncwarp();
        float s0 = 0.f, s1 = 0.f;
        #pragma unroll
        for (int d = 0; d < HDK; d++) {
            float qv = qs[w][d];
            s0 = fmaf(qv, ks[lane][d], s0);
            if (lane < MTOK - 32) s1 = fmaf(qv, ks[lane + 32][d], s1);
        }
        s0 *= scale; s1 *= scale;
        float mx = fmaxf(s0, (lane < MTOK - 32) ? s1 : -1e30f);
        #pragma unroll
        for (int off = 16; off; off >>= 1) mx = fmaxf(mx, __shfl_xor_sync(0xffffffffu, mx, off));
        float e0 = expf(s0 - mx);
        float e1 = (lane < MTOK - 32) ? expf(s1 - mx) : 0.f;
        float sm = e0 + e1;
        #pragma unroll
        for (int off = 16; off; off >>= 1) sm += __shfl_xor_sync(0xffffffffu, sm, off);
        float inv = 1.f / sm;
        ps[w][lane] = e0 * inv;
        if (lane < MTOK - 32) ps[w][lane + 32] = e1 * inv;
        __syncwarp();
        float a0 = 0.f, a1 = 0.f;
        #pragma unroll
        for (int m = 0; m < MTOK; m++) {
            float p = ps[w][m];
            a0 = fmaf(p, vs[m][lane], a0);
            a1 = fmaf(p, vs[m][lane + 32], a1);
        }
        size_t o0 = ((size_t)(b * NTOK + n)) * CDIM + hh * HD + lane;
        oh[o0]      = __float2half_rn(a0);
        oh[o0 + 32] = __float2half_rn(a1);
        __syncwarp();
    }
}

// ---------------- host ----------------
static inline int cdiv(int a, int b) { return (a + b - 1) / b; }
#define SMEM_OF(BM, BN) (1024 + 3 * ((BM + BN) * RSTRIDE))

extern "C" void kernel_launch(void* const* d_in, const int* in_sizes, int n_in,
                              void* d_out, int out_size) {
    const float* x_in   = (const float*)d_in[0];
    const float* q_w    = (const float*)d_in[1];
    const float* dw_w   = (const float*)d_in[2];
    const float* dw_b   = (const float*)d_in[3];
    const float* pw_w   = (const float*)d_in[4];
    const float* pw_b   = (const float*)d_in[5];
    const float* lnr_g  = (const float*)d_in[6];
    const float* lnr_b  = (const float*)d_in[7];
    const float* k_w    = (const float*)d_in[8];
    const float* v_w    = (const float*)d_in[9];
    const float* proj_w = (const float*)d_in[10];
    const float* proj_b = (const float*)d_in[11];
    const float* ln1_g  = (const float*)d_in[12];
    const float* ln1_b  = (const float*)d_in[13];
    const float* ln2_g  = (const float*)d_in[14];
    const float* ln2_b  = (const float*)d_in[15];
    const float* fc1_w  = (const float*)d_in[16];
    const float* fc1_b  = (const float*)d_in[17];
    const float* fc2_w  = (const float*)d_in[18];
    const float* fc2_b  = (const float*)d_in[19];

    float* xcur = (float*)d_out;

    float* p_r0;
    __half *p_yh, *p_rch, *p_rh, *p_qh, *p_kh, *p_vh, *p_oh, *p_hh;
    __half *wq, *wpw, *wkv, *wp, *w1, *w2;
    cudaGetSymbolAddress((void**)&p_r0, g_r0);
    cudaGetSymbolAddress((void**)&p_yh, g_yh);   cudaGetSymbolAddress((void**)&p_rch, g_rch);
    cudaGetSymbolAddress((void**)&p_rh, g_rh);
    cudaGetSymbolAddress((void**)&p_qh, g_qh);   cudaGetSymbolAddress((void**)&p_kh, g_kh);
    cudaGetSymbolAddress((void**)&p_vh, g_vh);
    cudaGetSymbolAddress((void**)&p_oh, g_oh);   cudaGetSymbolAddress((void**)&p_hh, g_hh);
    cudaGetSymbolAddress((void**)&wq, g_wq);     cudaGetSymbolAddress((void**)&wpw, g_wpw);
    cudaGetSymbolAddress((void**)&wkv, g_wkv);
    cudaGetSymbolAddress((void**)&wp, g_wp);     cudaGetSymbolAddress((void**)&w1, g_w1);
    cudaGetSymbolAddress((void**)&w2, g_w2);

    cudaFuncSetAttribute(tcmm_kernel<64,64,2,2,1>,    cudaFuncAttributeMaxDynamicSharedMemorySize, SMEM_OF(64,64));
    cudaFuncSetAttribute(tcmm_kernel<64,64,2,2,5>,    cudaFuncAttributeMaxDynamicSharedMemorySize, SMEM_OF(64,64));
    cudaFuncSetAttribute(tcmm_kernel<128,64,4,2,4>,   cudaFuncAttributeMaxDynamicSharedMemorySize, SMEM_OF(128,64));
    cudaFuncSetAttribute(tcmm_kernel<128,128,4,2,2>,  cudaFuncAttributeMaxDynamicSharedMemorySize, SMEM_OF(128,128));
    cudaFuncSetAttribute(tcmm_kernel<128,128,4,2,3>,  cudaFuncAttributeMaxDynamicSharedMemorySize, SMEM_OF(128,128));

    // weight transpose, all layers batched via grid.z
    wsplit_kernel<<<dim3(CNEW/32,   CDIM/32,   LAYERS), 256>>>(q_w,    wq,  CDIM,   CNEW, (size_t)CDIM*CNEW);
    wsplit_kernel<<<dim3(CNEW/32,   CDIM/32,   LAYERS), 256>>>(pw_w,   wpw, CDIM,   CNEW, (size_t)CDIM*CNEW);
    wsplit_kernel<<<dim3(CNEW/32,   CNEW/32,   LAYERS), 256>>>(k_w,    wkv, CNEW,   CNEW, (size_t)NKV*CNEW);
    wsplit_kernel<<<dim3(CDIM/32,   CNEW/32,   LAYERS), 256>>>(v_w,    wkv + (size_t)CNEW*CNEW,
                                                               CNEW,   CDIM, (size_t)NKV*CNEW);
    wsplit_kernel<<<dim3(CDIM/32,   CDIM/32,   LAYERS), 256>>>(proj_w, wp,  CDIM,   CDIM, (size_t)CDIM*CDIM);
    wsplit_kernel<<<dim3(HIDDIM/32, CDIM/32,   LAYERS), 256>>>(fc1_w,  w1,  CDIM,   HIDDIM, (size_t)CDIM*HIDDIM);
    wsplit_kernel<<<dim3(CDIM/32,   HIDDIM/32, LAYERS), 256>>>(fc2_w,  w2,  HIDDIM, CDIM, (size_t)HIDDIM*CDIM);

    for (int l = 0; l < LAYERS; l++) {
        const float* xin = (l == 0) ? x_in : xcur;   // layer 0 reads harness input
        // y = LN1(x) -> fp16
        ln_kernel<<<cdiv(ROWS_X,8), 256>>>(xin, p_yh,
            ln1_g + l*CDIM, ln1_b + l*CDIM, CDIM, 1e-6f, 0, ROWS_X);
        dwconv_kernel<<<dim3(MTOK, BATCH), 256>>>(p_yh, dw_w + (size_t)l*CDIM*4,
                                                  dw_b + l*CDIM, p_rch);
        // r0 = rconv @ pw + b   (3136 x 960, K=768)
        tcmm_kernel<64,64,2,2,1><<<dim3(CNEW/64, ROWS_R/64), 128, SMEM_OF(64,64)>>>(
            p_rch, wpw + (size_t)l*CNEW*CDIM,
            pw_b + l*CNEW, nullptr, p_r0, nullptr, nullptr, ROWS_R, CNEW, CDIM);
        // r = gelu(LN(r0)) -> fp16
        ln_kernel<<<cdiv(ROWS_R,8), 256>>>(p_r0, p_rh,
            lnr_g + l*CNEW, lnr_b + l*CNEW, CNEW, 1e-5f, 1, ROWS_R);
        // q = y @ q_w -> fp16   (12544 x 960, K=768)
        tcmm_kernel<128,64,4,2,4><<<dim3(CNEW/64, ROWS_X/128), 256, SMEM_OF(128,64)>>>(
            p_yh, wq + (size_t)l*CNEW*CDIM,
            nullptr, nullptr, nullptr, p_qh, nullptr, ROWS_X, CNEW, CDIM);
        // k|v = r @ [k_w; v_w] -> fp16 split   (3136 x 1728, K=960)
        tcmm_kernel<64,64,2,2,5><<<dim3(NKV/64, ROWS_R/64), 128, SMEM_OF(64,64)>>>(
            p_rh, wkv + (size_t)l*NKV*CNEW,
            nullptr, nullptr, nullptr, p_kh, p_vh, ROWS_R, NKV, CNEW);
        attn_kernel<<<BATCH*NHEAD, 256>>>(p_qh, p_kh, p_vh, p_oh);
        // x(out) = resid + o @ proj + b   (12544 x 768, K=768)
        tcmm_kernel<128,128,4,2,3><<<dim3(CDIM/128, ROWS_X/128), 256, SMEM_OF(128,128)>>>(
            p_oh, wp + (size_t)l*CDIM*CDIM,
            proj_b + l*CDIM, xin, xcur, nullptr, nullptr, ROWS_X, CDIM, CDIM);
        // z = LN2(x) -> fp16
        ln_kernel<<<cdiv(ROWS_X,8), 256>>>(xcur, p_yh,
            ln2_g + l*CDIM, ln2_b + l*CDIM, CDIM, 1e-6f, 0, ROWS_X);
        // h = gelu(z @ fc1 + b) -> fp16  (12544 x 3072, K=768)
        tcmm_kernel<128,128,4,2,2><<<dim3(HIDDIM/128, ROWS_X/128), 256, SMEM_OF(128,128)>>>(
            p_yh, w1 + (size_t)l*HIDDIM*CDIM,
            fc1_b + l*HIDDIM, nullptr, nullptr, p_hh, nullptr, ROWS_X, HIDDIM, CDIM);
        // x += h @ fc2 + b      (12544 x 768, K=3072)
        tcmm_kernel<128,128,4,2,3><<<dim3(CDIM/128, ROWS_X/128), 256, SMEM_OF(128,128)>>>(
            p_hh, w2 + (size_t)l*CDIM*HIDDIM,
            fc2_b + l*CDIM, xcur, xcur, nullptr, nullptr, ROWS_X, CDIM, HIDDIM);
    }
}

// round 16
// speedup vs baseline: 1.3745x; 1.3221x over previous
#include <cuda_runtime.h>
#include <cuda_fp16.h>
#include <math.h>
#include <stdint.h>

#define LAYERS 4
#define BATCH  64
#define NTOK   196
#define CDIM   768
#define CNEW   960
#define HIDDIM 3072
#define NHEAD  12
#define HD     64
#define HDK    80
#define MTOK   49
#define HW     14
#define ROWS_X (BATCH * NTOK)   // 12544
#define ROWS_R (BATCH * MTOK)   // 3136
#define NKV    (CNEW + CDIM)    // 1728

// ---------------- scratch ----------------
__device__ float g_r0[ROWS_R * CNEW];
__device__ __align__(16) __half g_yh[ROWS_X * CDIM];
__device__ __align__(16) __half g_rch[ROWS_R * CDIM];
__device__ __align__(16) __half g_rh[ROWS_R * CNEW];
__device__ __align__(16) __half g_qh[ROWS_X * CNEW];
__device__ __align__(16) __half g_kh[ROWS_R * CNEW];
__device__ __align__(16) __half g_vh[ROWS_R * CDIM];
__device__ __align__(16) __half g_oh[ROWS_X * CDIM];
__device__ __align__(16) __half g_hh[ROWS_X * HIDDIM];

// transposed weights, [N][K] K-major fp16
__device__ __align__(16) __half g_wq [LAYERS*CNEW*CDIM];
__device__ __align__(16) __half g_wpw[LAYERS*CNEW*CDIM];
__device__ __align__(16) __half g_wkv[LAYERS*NKV*CNEW];
__device__ __align__(16) __half g_wp [LAYERS*CDIM*CDIM];
__device__ __align__(16) __half g_w1 [LAYERS*HIDDIM*CDIM];
__device__ __align__(16) __half g_w2 [LAYERS*CDIM*HIDDIM];

// ---------------- helpers ----------------
__device__ __forceinline__ uint32_t smem_u32(const void* p) {
    uint32_t a;
    asm("{ .reg .u64 t; cvta.to.shared.u64 t, %1; cvt.u32.u64 %0, t; }" : "=r"(a) : "l"(p));
    return a;
}
__device__ __forceinline__ void cp16(uint32_t dst, const void* src) {
    asm volatile("cp.async.cg.shared.global [%0], [%1], 16;" :: "r"(dst), "l"(src));
}
__device__ __forceinline__ void cp_commit() { asm volatile("cp.async.commit_group;" ::: "memory"); }
template <int N> __device__ __forceinline__ void cp_wait() {
    asm volatile("cp.async.wait_group %0;" :: "n"(N) : "memory");
}
__device__ __forceinline__ void ldsm_x4(uint32_t (&r)[4], uint32_t addr) {
    asm volatile("ldmatrix.sync.aligned.m8n8.x4.shared.b16 {%0,%1,%2,%3}, [%4];"
        : "=r"(r[0]), "=r"(r[1]), "=r"(r[2]), "=r"(r[3]) : "r"(addr));
}
__device__ __forceinline__ void ldsm_x4_t(uint32_t (&r)[4], uint32_t addr) {
    asm volatile("ldmatrix.sync.aligned.m8n8.x4.trans.shared.b16 {%0,%1,%2,%3}, [%4];"
        : "=r"(r[0]), "=r"(r[1]), "=r"(r[2]), "=r"(r[3]) : "r"(addr));
}
__device__ __forceinline__ void mma16816(float (&d)[4], const uint32_t (&a)[4],
                                         uint32_t b0, uint32_t b1) {
    asm volatile("mma.sync.aligned.m16n8k16.row.col.f32.f16.f16.f32 "
        "{%0,%1,%2,%3}, {%4,%5,%6,%7}, {%8,%9}, {%0,%1,%2,%3};"
        : "+f"(d[0]), "+f"(d[1]), "+f"(d[2]), "+f"(d[3])
        : "r"(a[0]), "r"(a[1]), "r"(a[2]), "r"(a[3]), "r"(b0), "r"(b1));
}
__device__ __forceinline__ float gelu_exact(float x) {
    return 0.5f * x * (1.0f + erff(x * 0.7071067811865476f));
}

// ---------------- weight transpose -> fp16 (z = layer) ----------------
__global__ __launch_bounds__(256) void wsplit_kernel(
        const float* __restrict__ W, __half* __restrict__ T, int K, int N,
        size_t dstStride) {
    const float* Wl = W + (size_t)blockIdx.z * K * N;
    __half* Tl = T + (size_t)blockIdx.z * dstStride;
    __shared__ float t[32][33];
    const int n0 = blockIdx.x * 32, k0 = blockIdx.y * 32;
    const int tx = threadIdx.x & 31, ty = threadIdx.x >> 5;
    #pragma unroll
    for (int i = 0; i < 4; i++) {
        int k = ty + i * 8;
        t[k][tx] = Wl[(size_t)(k0 + k) * N + n0 + tx];
    }
    __syncthreads();
    #pragma unroll
    for (int i = 0; i < 4; i++) {
        int n = ty + i * 8;
        Tl[(size_t)(n0 + n) * K + k0 + tx] = __float2half_rn(t[tx][n]);
    }
}

// ---------------- LayerNorm (+gelu), warp-per-row, float4, fp16 out ----------------
__global__ __launch_bounds__(256) void ln_kernel(
        const float* __restrict__ in, __half* __restrict__ oh,
        const float* __restrict__ gamma, const float* __restrict__ beta,
        int W, float eps, int do_gelu, int rows) {
    const int w = threadIdx.x >> 5, lane = threadIdx.x & 31;
    const int row = blockIdx.x * 8 + w;
    if (row >= rows) return;
    const float4* p = (const float4*)(in + (size_t)row * W);
    const int W4 = W >> 2;
    float s = 0.f, ss = 0.f;
    for (int j = lane; j < W4; j += 32) {
        float4 v = p[j];
        s  += (v.x + v.y) + (v.z + v.w);
        ss += (v.x * v.x + v.y * v.y) + (v.z * v.z + v.w * v.w);
    }
    #pragma unroll
    for (int off = 16; off; off >>= 1) {
        s  += __shfl_xor_sync(0xffffffffu, s, off);
        ss += __shfl_xor_sync(0xffffffffu, ss, off);
    }
    const float mean = s / (float)W;
    const float var  = ss / (float)W - mean * mean;
    const float inv  = rsqrtf(var + eps);
    const float4* g4 = (const float4*)gamma;
    const float4* b4 = (const float4*)beta;
    uint2* o4 = (uint2*)(oh + (size_t)row * W);
    for (int j = lane; j < W4; j += 32) {
        float4 v = p[j], g = g4[j], b = b4[j];
        float v0 = (v.x - mean) * inv * g.x + b.x;
        float v1 = (v.y - mean) * inv * g.y + b.y;
        float v2 = (v.z - mean) * inv * g.z + b.z;
        float v3 = (v.w - mean) * inv * g.w + b.w;
        if (do_gelu) {
            v0 = gelu_exact(v0); v1 = gelu_exact(v1);
            v2 = gelu_exact(v2); v3 = gelu_exact(v3);
        }
        __half2 lo; lo.x = __float2half_rn(v0); lo.y = __float2half_rn(v1);
        __half2 hi; hi.x = __float2half_rn(v2); hi.y = __float2half_rn(v3);
        uint2 o; o.x = *(uint32_t*)&lo; o.y = *(uint32_t*)&hi;
        o4[j] = o;
    }
}

// ---------------- depthwise 2x2/s2 conv, fp16 in -> fp16 out ----------------
__global__ void dwconv_kernel(const __half* __restrict__ y,
                              const float* __restrict__ w4, const float* __restrict__ bias,
                              __half* __restrict__ oh) {
    const int m = blockIdx.x, b = blockIdx.y;
    const int h7 = m / 7, w7 = m % 7;
    const int p00 = (h7 * 2) * HW + w7 * 2;
    const __half* yb = y + (size_t)b * NTOK * CDIM;
    const size_t ob = ((size_t)b * MTOK + m) * CDIM;
    for (int c = threadIdx.x; c < CDIM; c += blockDim.x) {
        float acc = __half2float(yb[(size_t)(p00         ) * CDIM + c]) * w4[c * 4 + 0]
                  + __half2float(yb[(size_t)(p00 + 1     ) * CDIM + c]) * w4[c * 4 + 1]
                  + __half2float(yb[(size_t)(p00 + HW    ) * CDIM + c]) * w4[c * 4 + 2]
                  + __half2float(yb[(size_t)(p00 + HW + 1) * CDIM + c]) * w4[c * 4 + 3]
                  + bias[c];
        oh[ob + c] = __float2half_rn(acc);
    }
}

// ---------------------------------------------------------------------------
// fp16 GEMM on HMMA (R12 known-good shapes)
// ---------------------------------------------------------------------------
#define RSTRIDE 144

template <int BM, int BN, int NM, int NN, int EPI>
__global__ __launch_bounds__(32*NM*NN, 512/(32*NM*NN)) void tcmm_kernel(
        const __half* __restrict__ A, const __half* __restrict__ B,
        const float* __restrict__ bias, const float* __restrict__ resid,
        float* __restrict__ Cf, __half* __restrict__ Ch, __half* __restrict__ Ch2,
        int M, int N, int K) {
    constexpr int NT   = 32 * NM * NN;
    constexpr int SS   = (BM + BN) * RSTRIDE;
    constexpr int WN   = BN / NN;
    constexpr int WN8  = WN / 8;
    constexpr int WN16 = WN / 16;
    static_assert(BM / NM == 32, "each warp covers 32 rows (2 mt tiles)");
    extern __shared__ char smem[];
    const int tid = threadIdx.x, lane = tid & 31, wid = tid >> 5;
    const int wn = wid % NN, wm = wid / NN;
    const int row0 = blockIdx.y * BM, col0 = blockIdx.x * BN;
    const uint32_t tiles = (smem_u32(smem) + 1023) & ~1023u;

    float acc[2][WN8][4];
    #pragma unroll
    for (int a = 0; a < 2; a++)
        #pragma unroll
        for (int b = 0; b < WN8; b++)
            #pragma unroll
            for (int c = 0; c < 4; c++) acc[a][b][c] = 0.f;

    const int NC = K >> 6;   // BK = 64

    auto load_chunk = [&](int stage, int k0) {
        uint32_t sd = tiles + stage * SS;
        #pragma unroll
        for (int i = 0; i < BM * 8 / NT; i++) {
            int idx = tid + i * NT;
            int row = idx >> 3, cc = idx & 7;
            int grow = row0 + row; if (grow > M - 1) grow = M - 1;
            cp16(sd + row * RSTRIDE + cc * 16, A + (size_t)grow * K + k0 + cc * 8);
        }
        #pragma unroll
        for (int i = 0; i < BN * 8 / NT; i++) {
            int idx = tid + i * NT;
            int row = idx >> 3, cc = idx & 7;
            cp16(sd + BM * RSTRIDE + row * RSTRIDE + cc * 16,
                 B + (size_t)(col0 + row) * K + k0 + cc * 8);
        }
    };

    load_chunk(0, 0);  cp_commit();
    load_chunk(1, 64); cp_commit();

    for (int c = 0; c < NC; c++) {
        if (c + 2 < NC) cp_wait<1>(); else cp_wait<0>();
        __syncthreads();
        if (c + 2 < NC) { load_chunk((c + 2) % 3, (c + 2) * 64); cp_commit(); }

        const uint32_t sA = tiles + (c % 3) * SS;
        const uint32_t sB = sA + BM * RSTRIDE;
        #pragma unroll
        for (int ks = 0; ks < 4; ks++) {
            uint32_t ah[2][4];
            #pragma unroll
            for (int mt = 0; mt < 2; mt++) {
                uint32_t r = sA + (wm * 32 + mt * 16 + (lane & 15)) * RSTRIDE
                           + (2 * ks + (lane >> 4)) * 16;
                ldsm_x4(ah[mt], r);
            }
            uint32_t bh[WN16][4];
            #pragma unroll
            for (int g = 0; g < WN16; g++) {
                int rrow = wn * WN + g * 16 + (lane & 7) + ((lane >> 4) << 3);
                uint32_t r = sB + rrow * RSTRIDE + (2 * ks + ((lane >> 3) & 1)) * 16;
                ldsm_x4(bh[g], r);
            }
            #pragma unroll
            for (int mt = 0; mt < 2; mt++)
                #pragma unroll
                for (int g = 0; g < WN16; g++) {
                    mma16816(acc[mt][2*g],   ah[mt], bh[g][0], bh[g][1]);
                    mma16816(acc[mt][2*g+1], ah[mt], bh[g][2], bh[g][3]);
                }
        }
    }

    const int er = lane >> 2, ec = (lane & 3) * 2;
    #pragma unroll
    for (int mt = 0; mt < 2; mt++) {
        #pragma unroll
        for (int g = 0; g < WN8; g++) {
            const int gn = col0 + wn * WN + g * 8 + ec;
            #pragma unroll
            for (int hrow = 0; hrow < 2; hrow++) {
                const int gm = row0 + wm * 32 + mt * 16 + er + hrow * 8;
                if (gm >= M) continue;
                float v0 = acc[mt][g][2 * hrow];
                float v1 = acc[mt][g][2 * hrow + 1];
                if constexpr (EPI == 1 || EPI == 2 || EPI == 3) {
                    v0 += bias[gn]; v1 += bias[gn + 1];
                }
                if constexpr (EPI == 2) { v0 = gelu_exact(v0); v1 = gelu_exact(v1); }
                if constexpr (EPI == 2 || EPI == 4) {
                    __half2 hp; hp.x = __float2half_rn(v0); hp.y = __float2half_rn(v1);
                    *(__half2*)(Ch + (size_t)gm * N + gn) = hp;
                } else if constexpr (EPI == 5) {
                    __half2 hp; hp.x = __float2half_rn(v0); hp.y = __float2half_rn(v1);
                    if (gn < CNEW) *(__half2*)(Ch  + (size_t)gm * CNEW + gn) = hp;
                    else           *(__half2*)(Ch2 + (size_t)gm * CDIM + gn - CNEW) = hp;
                } else {
                    const size_t base = (size_t)gm * N + gn;
                    if constexpr (EPI == 3) {
                        float2 rs = *(const float2*)(resid + base);
                        v0 += rs.x; v1 += rs.y;
                    }
                    float2 o; o.x = v0; o.y = v1;
                    *(float2*)(Cf + base) = o;
                }
            }
        }
    }
}

// ---------------------------------------------------------------------------
// Tensor-core attention: per (b,h) block, 4 warps.
// K staged 64x80 (tokens padded, zero-filled) stride 176B; V staged 64x64
// stride 144B. QK^T via mma (Q A-frags from gmem), exact softmax in regs,
// P repacked to A-frags, AV via ldmatrix.trans on V[token][feature].
// ---------------------------------------------------------------------------
#define KSTR 176
#define VSTR 144

__global__ __launch_bounds__(128) void attn_tc_kernel(
        const __half* __restrict__ q, const __half* __restrict__ k,
        const __half* __restrict__ v, __half* __restrict__ oh) {
    __shared__ __align__(16) uint8_t ksm[64 * KSTR];
    __shared__ __align__(16) uint8_t vsm[64 * VSTR];
    const int bh = blockIdx.x;
    const int b = bh / NHEAD, hh = bh % NHEAD;
    const int tid = threadIdx.x, lane = tid & 31, wid = tid >> 5;
    const uint32_t ks0 = smem_u32(ksm), vs0 = smem_u32(vsm);

    const __half* kb = k + (size_t)b * MTOK * CNEW + hh * HDK;
    for (int i = tid; i < 64 * 10; i += 128) {        // K: 64 rows x 80 halves
        int r = i / 10, cc = i % 10;
        uint4 val = make_uint4(0u, 0u, 0u, 0u);
        if (r < MTOK) val = *(const uint4*)(kb + (size_t)r * CNEW + cc * 8);
        *(uint4*)(ksm + r * KSTR + cc * 16) = val;
    }
    const __half* vb = v + (size_t)b * MTOK * CDIM + hh * HD;
    for (int i = tid; i < 64 * 8; i += 128) {         // V: 64 rows x 64 halves
        int r = i / 8, cc = i % 8;
        uint4 val = make_uint4(0u, 0u, 0u, 0u);
        if (r < MTOK) val = *(const uint4*)(vb + (size_t)r * CDIM + cc * 8);
        *(uint4*)(vsm + r * VSTR + cc * 16) = val;
    }
    __syncthreads();

    const float scale = rsqrtf(80.0f);
    const __half* qb = q + (size_t)b * NTOK * CNEW + hh * HDK;

    for (int t = wid; t < 13; t += 4) {
        const int row0 = t * 16;
        int r0 = row0 + (lane >> 2);
        int r1 = r0 + 8;
        const int r0c = (r0 > NTOK - 1) ? NTOK - 1 : r0;
        const int r1c = (r1 > NTOK - 1) ? NTOK - 1 : r1;

        // ---- S = Q K^T ----
        float s[8][4];
        #pragma unroll
        for (int g = 0; g < 8; g++)
            #pragma unroll
            for (int j = 0; j < 4; j++) s[g][j] = 0.f;
        #pragma unroll
        for (int kq = 0; kq < 5; kq++) {
            uint32_t a[4];
            const int c0 = kq * 16 + (lane & 3) * 2;
            a[0] = *(const uint32_t*)(qb + (size_t)r0c * CNEW + c0);
            a[1] = *(const uint32_t*)(qb + (size_t)r1c * CNEW + c0);
            a[2] = *(const uint32_t*)(qb + (size_t)r0c * CNEW + c0 + 8);
            a[3] = *(const uint32_t*)(qb + (size_t)r1c * CNEW + c0 + 8);
            #pragma unroll
            for (int g2 = 0; g2 < 4; g2++) {
                uint32_t bk[4];
                uint32_t addr = ks0 + (g2 * 16 + (lane & 7) + ((lane >> 4) << 3)) * KSTR
                              + kq * 32 + (((lane >> 3) & 1) << 4);
                ldsm_x4(bk, addr);
                mma16816(s[2*g2],   a, bk[0], bk[1]);
                mma16816(s[2*g2+1], a, bk[2], bk[3]);
            }
        }

        // ---- softmax (exact, cols >= MTOK masked) ----
        float mx0 = -1e30f, mx1 = -1e30f;
        #pragma unroll
        for (int g = 0; g < 8; g++) {
            const int c = g * 8 + (lane & 3) * 2;
            s[g][0] = (c     < MTOK) ? s[g][0] * scale : -1e30f;
            s[g][1] = (c + 1 < MTOK) ? s[g][1] * scale : -1e30f;
            s[g][2] = (c     < MTOK) ? s[g][2] * scale : -1e30f;
            s[g][3] = (c + 1 < MTOK) ? s[g][3] * scale : -1e30f;
            mx0 = fmaxf(mx0, fmaxf(s[g][0], s[g][1]));
            mx1 = fmaxf(mx1, fmaxf(s[g][2], s[g][3]));
        }
        #pragma unroll
        for (int off = 1; off <= 2; off <<= 1) {
            mx0 = fmaxf(mx0, __shfl_xor_sync(0xffffffffu, mx0, off));
            mx1 = fmaxf(mx1, __shfl_xor_sync(0xffffffffu, mx1, off));
        }
        float sm0 = 0.f, sm1 = 0.f;
        #pragma unroll
        for (int g = 0; g < 8; g++) {
            s[g][0] = __expf(s[g][0] - mx0);
            s[g][1] = __expf(s[g][1] - mx0);
            s[g][2] = __expf(s[g][2] - mx1);
            s[g][3] = __expf(s[g][3] - mx1);
            sm0 += s[g][0] + s[g][1];
            sm1 += s[g][2] + s[g][3];
        }
        #pragma unroll
        for (int off = 1; off <= 2; off <<= 1) {
            sm0 += __shfl_xor_sync(0xffffffffu, sm0, off);
            sm1 += __shfl_xor_sync(0xffffffffu, sm1, off);
        }
        const float inv0 = 1.f / sm0, inv1 = 1.f / sm1;

        // ---- O = P V ----
        float o[8][4];
        #pragma unroll
        for (int g = 0; g < 8; g++)
            #pragma unroll
            for (int j = 0; j < 4; j++) o[g][j] = 0.f;
        #pragma unroll
        for (int kt = 0; kt < 4; kt++) {
            uint32_t a[4];
            __half2 p;
            p.x = __float2half_rn(s[2*kt][0]);   p.y = __float2half_rn(s[2*kt][1]);
            a[0] = *(uint32_t*)&p;
            p.x = __float2half_rn(s[2*kt][2]);   p.y = __float2half_rn(s[2*kt][3]);
            a[1] = *(uint32_t*)&p;
            p.x = __float2half_rn(s[2*kt+1][0]); p.y = __float2half_rn(s[2*kt+1][1]);
            a[2] = *(uint32_t*)&p;
            p.x = __float2half_rn(s[2*kt+1][2]); p.y = __float2half_rn(s[2*kt+1][3]);
            a[3] = *(uint32_t*)&p;
            #pragma unroll
            for (int n2 = 0; n2 < 4; n2++) {
                uint32_t bv[4];
                uint32_t addr = vs0 + (kt * 16 + (lane & 15)) * VSTR
                              + n2 * 32 + ((lane >> 4) << 4);
                ldsm_x4_t(bv, addr);
                mma16816(o[2*n2],   a, bv[0], bv[1]);
                mma16816(o[2*n2+1], a, bv[2], bv[3]);
            }
        }

        // ---- store ----
        #pragma unroll
        for (int g = 0; g < 8; g++) {
            const int c = g * 8 + (lane & 3) * 2;
            if (r0 < NTOK) {
                __half2 hp;
                hp.x = __float2half_rn(o[g][0] * inv0);
                hp.y = __float2half_rn(o[g][1] * inv0);
                *(__half2*)(oh + ((size_t)(b * NTOK + r0)) * CDIM + hh * HD + c) = hp;
            }
            if (r1 < NTOK) {
                __half2 hp;
                hp.x = __float2half_rn(o[g][2] * inv1);
                hp.y = __float2half_rn(o[g][3] * inv1);
                *(__half2*)(oh + ((size_t)(b * NTOK + r1)) * CDIM + hh * HD + c) = hp;
            }
        }
    }
}

// ---------------- host ----------------
static inline int cdiv(int a, int b) { return (a + b - 1) / b; }
#define SMEM_OF(BM, BN) (1024 + 3 * ((BM + BN) * RSTRIDE))

extern "C" void kernel_launch(void* const* d_in, const int* in_sizes, int n_in,
                              void* d_out, int out_size) {
    const float* x_in   = (const float*)d_in[0];
    const float* q_w    = (const float*)d_in[1];
    const float* dw_w   = (const float*)d_in[2];
    const float* dw_b   = (const float*)d_in[3];
    const float* pw_w   = (const float*)d_in[4];
    const float* pw_b   = (const float*)d_in[5];
    const float* lnr_g  = (const float*)d_in[6];
    const float* lnr_b  = (const float*)d_in[7];
    const float* k_w    = (const float*)d_in[8];
    const float* v_w    = (const float*)d_in[9];
    const float* proj_w = (const float*)d_in[10];
    const float* proj_b = (const float*)d_in[11];
    const float* ln1_g  = (const float*)d_in[12];
    const float* ln1_b  = (const float*)d_in[13];
    const float* ln2_g  = (const float*)d_in[14];
    const float* ln2_b  = (const float*)d_in[15];
    const float* fc1_w  = (const float*)d_in[16];
    const float* fc1_b  = (const float*)d_in[17];
    const float* fc2_w  = (const float*)d_in[18];
    const float* fc2_b  = (const float*)d_in[19];

    float* xcur = (float*)d_out;

    float* p_r0;
    __half *p_yh, *p_rch, *p_rh, *p_qh, *p_kh, *p_vh, *p_oh, *p_hh;
    __half *wq, *wpw, *wkv, *wp, *w1, *w2;
    cudaGetSymbolAddress((void**)&p_r0, g_r0);
    cudaGetSymbolAddress((void**)&p_yh, g_yh);   cudaGetSymbolAddress((void**)&p_rch, g_rch);
    cudaGetSymbolAddress((void**)&p_rh, g_rh);
    cudaGetSymbolAddress((void**)&p_qh, g_qh);   cudaGetSymbolAddress((void**)&p_kh, g_kh);
    cudaGetSymbolAddress((void**)&p_vh, g_vh);
    cudaGetSymbolAddress((void**)&p_oh, g_oh);   cudaGetSymbolAddress((void**)&p_hh, g_hh);
    cudaGetSymbolAddress((void**)&wq, g_wq);     cudaGetSymbolAddress((void**)&wpw, g_wpw);
    cudaGetSymbolAddress((void**)&wkv, g_wkv);
    cudaGetSymbolAddress((void**)&wp, g_wp);     cudaGetSymbolAddress((void**)&w1, g_w1);
    cudaGetSymbolAddress((void**)&w2, g_w2);

    cudaFuncSetAttribute(tcmm_kernel<64,64,2,2,1>,    cudaFuncAttributeMaxDynamicSharedMemorySize, SMEM_OF(64,64));
    cudaFuncSetAttribute(tcmm_kernel<64,64,2,2,5>,    cudaFuncAttributeMaxDynamicSharedMemorySize, SMEM_OF(64,64));
    cudaFuncSetAttribute(tcmm_kernel<128,64,4,2,4>,   cudaFuncAttributeMaxDynamicSharedMemorySize, SMEM_OF(128,64));
    cudaFuncSetAttribute(tcmm_kernel<128,128,4,2,2>,  cudaFuncAttributeMaxDynamicSharedMemorySize, SMEM_OF(128,128));
    cudaFuncSetAttribute(tcmm_kernel<128,128,4,2,3>,  cudaFuncAttributeMaxDynamicSharedMemorySize, SMEM_OF(128,128));

    // weight transpose, all layers batched via grid.z
    wsplit_kernel<<<dim3(CNEW/32,   CDIM/32,   LAYERS), 256>>>(q_w,    wq,  CDIM,   CNEW, (size_t)CDIM*CNEW);
    wsplit_kernel<<<dim3(CNEW/32,   CDIM/32,   LAYERS), 256>>>(pw_w,   wpw, CDIM,   CNEW, (size_t)CDIM*CNEW);
    wsplit_kernel<<<dim3(CNEW/32,   CNEW/32,   LAYERS), 256>>>(k_w,    wkv, CNEW,   CNEW, (size_t)NKV*CNEW);
    wsplit_kernel<<<dim3(CDIM/32,   CNEW/32,   LAYERS), 256>>>(v_w,    wkv + (size_t)CNEW*CNEW,
                                                               CNEW,   CDIM, (size_t)NKV*CNEW);
    wsplit_kernel<<<dim3(CDIM/32,   CDIM/32,   LAYERS), 256>>>(proj_w, wp,  CDIM,   CDIM, (size_t)CDIM*CDIM);
    wsplit_kernel<<<dim3(HIDDIM/32, CDIM/32,   LAYERS), 256>>>(fc1_w,  w1,  CDIM,   HIDDIM, (size_t)CDIM*HIDDIM);
    wsplit_kernel<<<dim3(CDIM/32,   HIDDIM/32, LAYERS), 256>>>(fc2_w,  w2,  HIDDIM, CDIM, (size_t)HIDDIM*CDIM);

    for (int l = 0; l < LAYERS; l++) {
        const float* xin = (l == 0) ? x_in : xcur;
        ln_kernel<<<cdiv(ROWS_X,8), 256>>>(xin, p_yh,
            ln1_g + l*CDIM, ln1_b + l*CDIM, CDIM, 1e-6f, 0, ROWS_X);
        dwconv_kernel<<<dim3(MTOK, BATCH), 256>>>(p_yh, dw_w + (size_t)l*CDIM*4,
                                                  dw_b + l*CDIM, p_rch);
        tcmm_kernel<64,64,2,2,1><<<dim3(CNEW/64, ROWS_R/64), 128, SMEM_OF(64,64)>>>(
            p_rch, wpw + (size_t)l*CNEW*CDIM,
            pw_b + l*CNEW, nullptr, p_r0, nullptr, nullptr, ROWS_R, CNEW, CDIM);
        ln_kernel<<<cdiv(ROWS_R,8), 256>>>(p_r0, p_rh,
            lnr_g + l*CNEW, lnr_b + l*CNEW, CNEW, 1e-5f, 1, ROWS_R);
        tcmm_kernel<128,64,4,2,4><<<dim3(CNEW/64, ROWS_X/128), 256, SMEM_OF(128,64)>>>(
            p_yh, wq + (size_t)l*CNEW*CDIM,
            nullptr, nullptr, nullptr, p_qh, nullptr, ROWS_X, CNEW, CDIM);
        tcmm_kernel<64,64,2,2,5><<<dim3(NKV/64, ROWS_R/64), 128, SMEM_OF(64,64)>>>(
            p_rh, wkv + (size_t)l*NKV*CNEW,
            nullptr, nullptr, nullptr, p_kh, p_vh, ROWS_R, NKV, CNEW);
        attn_tc_kernel<<<BATCH*NHEAD, 128>>>(p_qh, p_kh, p_vh, p_oh);
        tcmm_kernel<128,128,4,2,3><<<dim3(CDIM/128, ROWS_X/128), 256, SMEM_OF(128,128)>>>(
            p_oh, wp + (size_t)l*CDIM*CDIM,
            proj_b + l*CDIM, xin, xcur, nullptr, nullptr, ROWS_X, CDIM, CDIM);
        ln_kernel<<<cdiv(ROWS_X,8), 256>>>(xcur, p_yh,
            ln2_g + l*CDIM, ln2_b + l*CDIM, CDIM, 1e-6f, 0, ROWS_X);
        tcmm_kernel<128,128,4,2,2><<<dim3(HIDDIM/128, ROWS_X/128), 256, SMEM_OF(128,128)>>>(
            p_yh, w1 + (size_t)l*HIDDIM*CDIM,
            fc1_b + l*HIDDIM, nullptr, nullptr, p_hh, nullptr, ROWS_X, HIDDIM, CDIM);
        tcmm_kernel<128,128,4,2,3><<<dim3(CDIM/128, ROWS_X/128), 256, SMEM_OF(128,128)>>>(
            p_hh, w2 + (size_t)l*CDIM*HIDDIM,
            fc2_b + l*CDIM, xcur, xcur, nullptr, nullptr, ROWS_X, CDIM, HIDDIM);
    }
}

// round 17
// speedup vs baseline: 1.3854x; 1.0079x over previous
#include <cuda_runtime.h>
#include <cuda_fp16.h>
#include <math.h>
#include <stdint.h>

#define LAYERS 4
#define BATCH  64
#define NTOK   196
#define CDIM   768
#define CNEW   960
#define HIDDIM 3072
#define NHEAD  12
#define HD     64
#define HDK    80
#define MTOK   49
#define HW     14
#define ROWS_X (BATCH * NTOK)   // 12544
#define ROWS_R (BATCH * MTOK)   // 3136
#define NKV    (CNEW + CDIM)    // 1728

// ---------------- scratch ----------------
__device__ float g_r0[ROWS_R * CNEW];
__device__ __align__(16) __half g_yh[ROWS_X * CDIM];
__device__ __align__(16) __half g_rch[ROWS_R * CDIM];
__device__ __align__(16) __half g_rh[ROWS_R * CNEW];
__device__ __align__(16) __half g_qh[ROWS_X * CNEW];
__device__ __align__(16) __half g_kh[ROWS_R * CNEW];
__device__ __align__(16) __half g_vh[ROWS_R * CDIM];
__device__ __align__(16) __half g_oh[ROWS_X * CDIM];
__device__ __align__(16) __half g_hh[ROWS_X * HIDDIM];

// transposed weights, [N][K] K-major fp16
__device__ __align__(16) __half g_wq [LAYERS*CNEW*CDIM];
__device__ __align__(16) __half g_wpw[LAYERS*CNEW*CDIM];
__device__ __align__(16) __half g_wkv[LAYERS*NKV*CNEW];
__device__ __align__(16) __half g_wp [LAYERS*CDIM*CDIM];
__device__ __align__(16) __half g_w1 [LAYERS*HIDDIM*CDIM];
__device__ __align__(16) __half g_w2 [LAYERS*CDIM*HIDDIM];

// ---------------- helpers ----------------
__device__ __forceinline__ uint32_t smem_u32(const void* p) {
    uint32_t a;
    asm("{ .reg .u64 t; cvta.to.shared.u64 t, %1; cvt.u32.u64 %0, t; }" : "=r"(a) : "l"(p));
    return a;
}
__device__ __forceinline__ void cp16(uint32_t dst, const void* src) {
    asm volatile("cp.async.cg.shared.global [%0], [%1], 16;" :: "r"(dst), "l"(src));
}
__device__ __forceinline__ void cp_commit() { asm volatile("cp.async.commit_group;" ::: "memory"); }
template <int N> __device__ __forceinline__ void cp_wait() {
    asm volatile("cp.async.wait_group %0;" :: "n"(N) : "memory");
}
__device__ __forceinline__ void ldsm_x4(uint32_t (&r)[4], uint32_t addr) {
    asm volatile("ldmatrix.sync.aligned.m8n8.x4.shared.b16 {%0,%1,%2,%3}, [%4];"
        : "=r"(r[0]), "=r"(r[1]), "=r"(r[2]), "=r"(r[3]) : "r"(addr));
}
__device__ __forceinline__ void ldsm_x4_t(uint32_t (&r)[4], uint32_t addr) {
    asm volatile("ldmatrix.sync.aligned.m8n8.x4.trans.shared.b16 {%0,%1,%2,%3}, [%4];"
        : "=r"(r[0]), "=r"(r[1]), "=r"(r[2]), "=r"(r[3]) : "r"(addr));
}
__device__ __forceinline__ void mma16816(float (&d)[4], const uint32_t (&a)[4],
                                         uint32_t b0, uint32_t b1) {
    asm volatile("mma.sync.aligned.m16n8k16.row.col.f32.f16.f16.f32 "
        "{%0,%1,%2,%3}, {%4,%5,%6,%7}, {%8,%9}, {%0,%1,%2,%3};"
        : "+f"(d[0]), "+f"(d[1]), "+f"(d[2]), "+f"(d[3])
        : "r"(a[0]), "r"(a[1]), "r"(a[2]), "r"(a[3]), "r"(b0), "r"(b1));
}
__device__ __forceinline__ float gelu_exact(float x) {
    return 0.5f * x * (1.0f + erff(x * 0.7071067811865476f));
}

// ---------------- weight transpose -> fp16 (z = layer) ----------------
__global__ __launch_bounds__(256) void wsplit_kernel(
        const float* __restrict__ W, __half* __restrict__ T, int K, int N,
        size_t dstStride) {
    const float* Wl = W + (size_t)blockIdx.z * K * N;
    __half* Tl = T + (size_t)blockIdx.z * dstStride;
    __shared__ float t[32][33];
    const int n0 = blockIdx.x * 32, k0 = blockIdx.y * 32;
    const int tx = threadIdx.x & 31, ty = threadIdx.x >> 5;
    #pragma unroll
    for (int i = 0; i < 4; i++) {
        int k = ty + i * 8;
        t[k][tx] = Wl[(size_t)(k0 + k) * N + n0 + tx];
    }
    __syncthreads();
    #pragma unroll
    for (int i = 0; i < 4; i++) {
        int n = ty + i * 8;
        Tl[(size_t)(n0 + n) * K + k0 + tx] = __float2half_rn(t[tx][n]);
    }
}

// ---------------- LayerNorm (+gelu), warp-per-row, compile-time W ----------------
template <int W, int DO_GELU>
__global__ __launch_bounds__(256) void ln_kernel(
        const float* __restrict__ in, __half* __restrict__ oh,
        const float* __restrict__ gamma, const float* __restrict__ beta,
        float eps, int rows) {
    constexpr int W4 = W >> 2;
    constexpr int NJ = (W4 + 31) / 32;      // 6 for both 768 and 960 (30 lanes idle-tail ok)
    const int w = threadIdx.x >> 5, lane = threadIdx.x & 31;
    const int row = blockIdx.x * 8 + w;
    if (row >= rows) return;
    const float4* p = (const float4*)(in + (size_t)row * W);
    float4 vv[NJ];
    #pragma unroll
    for (int i = 0; i < NJ; i++) {
        int j = lane + i * 32;
        vv[i] = (j < W4) ? p[j] : make_float4(0.f, 0.f, 0.f, 0.f);
    }
    float s = 0.f, ss = 0.f;
    #pragma unroll
    for (int i = 0; i < NJ; i++) {
        float4 v = vv[i];
        s  += (v.x + v.y) + (v.z + v.w);
        ss += (v.x * v.x + v.y * v.y) + (v.z * v.z + v.w * v.w);
    }
    #pragma unroll
    for (int off = 16; off; off >>= 1) {
        s  += __shfl_xor_sync(0xffffffffu, s, off);
        ss += __shfl_xor_sync(0xffffffffu, ss, off);
    }
    const float mean = s / (float)W;
    const float var  = ss / (float)W - mean * mean;
    const float inv  = rsqrtf(var + eps);
    const float4* g4 = (const float4*)gamma;
    const float4* b4 = (const float4*)beta;
    uint2* o4 = (uint2*)(oh + (size_t)row * W);
    #pragma unroll
    for (int i = 0; i < NJ; i++) {
        int j = lane + i * 32;
        if (j >= W4) break;
        float4 v = vv[i], g = g4[j], b = b4[j];
        float v0 = (v.x - mean) * inv * g.x + b.x;
        float v1 = (v.y - mean) * inv * g.y + b.y;
        float v2 = (v.z - mean) * inv * g.z + b.z;
        float v3 = (v.w - mean) * inv * g.w + b.w;
        if (DO_GELU) {
            v0 = gelu_exact(v0); v1 = gelu_exact(v1);
            v2 = gelu_exact(v2); v3 = gelu_exact(v3);
        }
        __half2 lo; lo.x = __float2half_rn(v0); lo.y = __float2half_rn(v1);
        __half2 hi; hi.x = __float2half_rn(v2); hi.y = __float2half_rn(v3);
        uint2 o; o.x = *(uint32_t*)&lo; o.y = *(uint32_t*)&hi;
        o4[j] = o;
    }
}

// ---------------- depthwise 2x2/s2 conv, fp16 in -> fp16 out ----------------
__global__ void dwconv_kernel(const __half* __restrict__ y,
                              const float* __restrict__ w4, const float* __restrict__ bias,
                              __half* __restrict__ oh) {
    const int m = blockIdx.x, b = blockIdx.y;
    const int h7 = m / 7, w7 = m % 7;
    const int p00 = (h7 * 2) * HW + w7 * 2;
    const __half* yb = y + (size_t)b * NTOK * CDIM;
    const size_t ob = ((size_t)b * MTOK + m) * CDIM;
    for (int c = threadIdx.x; c < CDIM; c += blockDim.x) {
        float acc = __half2float(yb[(size_t)(p00         ) * CDIM + c]) * w4[c * 4 + 0]
                  + __half2float(yb[(size_t)(p00 + 1     ) * CDIM + c]) * w4[c * 4 + 1]
                  + __half2float(yb[(size_t)(p00 + HW    ) * CDIM + c]) * w4[c * 4 + 2]
                  + __half2float(yb[(size_t)(p00 + HW + 1) * CDIM + c]) * w4[c * 4 + 3]
                  + bias[c];
        oh[ob + c] = __float2half_rn(acc);
    }
}

// ---------------------------------------------------------------------------
// fp16 GEMM on HMMA (R12 known-good shapes)
// ---------------------------------------------------------------------------
#define RSTRIDE 144

template <int BM, int BN, int NM, int NN, int EPI>
__global__ __launch_bounds__(32*NM*NN, 512/(32*NM*NN)) void tcmm_kernel(
        const __half* __restrict__ A, const __half* __restrict__ B,
        const float* __restrict__ bias, const float* __restrict__ resid,
        float* __restrict__ Cf, __half* __restrict__ Ch, __half* __restrict__ Ch2,
        int M, int N, int K) {
    constexpr int NT   = 32 * NM * NN;
    constexpr int SS   = (BM + BN) * RSTRIDE;
    constexpr int WN   = BN / NN;
    constexpr int WN8  = WN / 8;
    constexpr int WN16 = WN / 16;
    static_assert(BM / NM == 32, "each warp covers 32 rows (2 mt tiles)");
    extern __shared__ char smem[];
    const int tid = threadIdx.x, lane = tid & 31, wid = tid >> 5;
    const int wn = wid % NN, wm = wid / NN;
    const int row0 = blockIdx.y * BM, col0 = blockIdx.x * BN;
    const uint32_t tiles = (smem_u32(smem) + 1023) & ~1023u;

    float acc[2][WN8][4];
    #pragma unroll
    for (int a = 0; a < 2; a++)
        #pragma unroll
        for (int b = 0; b < WN8; b++)
            #pragma unroll
            for (int c = 0; c < 4; c++) acc[a][b][c] = 0.f;

    const int NC = K >> 6;   // BK = 64

    auto load_chunk = [&](int stage, int k0) {
        uint32_t sd = tiles + stage * SS;
        #pragma unroll
        for (int i = 0; i < BM * 8 / NT; i++) {
            int idx = tid + i * NT;
            int row = idx >> 3, cc = idx & 7;
            int grow = row0 + row; if (grow > M - 1) grow = M - 1;
            cp16(sd + row * RSTRIDE + cc * 16, A + (size_t)grow * K + k0 + cc * 8);
        }
        #pragma unroll
        for (int i = 0; i < BN * 8 / NT; i++) {
            int idx = tid + i * NT;
            int row = idx >> 3, cc = idx & 7;
            cp16(sd + BM * RSTRIDE + row * RSTRIDE + cc * 16,
                 B + (size_t)(col0 + row) * K + k0 + cc * 8);
        }
    };

    load_chunk(0, 0);  cp_commit();
    load_chunk(1, 64); cp_commit();

    for (int c = 0; c < NC; c++) {
        if (c + 2 < NC) cp_wait<1>(); else cp_wait<0>();
        __syncthreads();
        if (c + 2 < NC) { load_chunk((c + 2) % 3, (c + 2) * 64); cp_commit(); }

        const uint32_t sA = tiles + (c % 3) * SS;
        const uint32_t sB = sA + BM * RSTRIDE;
        #pragma unroll
        for (int ks = 0; ks < 4; ks++) {
            uint32_t ah[2][4];
            #pragma unroll
            for (int mt = 0; mt < 2; mt++) {
                uint32_t r = sA + (wm * 32 + mt * 16 + (lane & 15)) * RSTRIDE
                           + (2 * ks + (lane >> 4)) * 16;
                ldsm_x4(ah[mt], r);
            }
            uint32_t bh[WN16][4];
            #pragma unroll
            for (int g = 0; g < WN16; g++) {
                int rrow = wn * WN + g * 16 + (lane & 7) + ((lane >> 4) << 3);
                uint32_t r = sB + rrow * RSTRIDE + (2 * ks + ((lane >> 3) & 1)) * 16;
                ldsm_x4(bh[g], r);
            }
            #pragma unroll
            for (int mt = 0; mt < 2; mt++)
                #pragma unroll
                for (int g = 0; g < WN16; g++) {
                    mma16816(acc[mt][2*g],   ah[mt], bh[g][0], bh[g][1]);
                    mma16816(acc[mt][2*g+1], ah[mt], bh[g][2], bh[g][3]);
                }
        }
    }

    const int er = lane >> 2, ec = (lane & 3) * 2;
    #pragma unroll
    for (int mt = 0; mt < 2; mt++) {
        #pragma unroll
        for (int g = 0; g < WN8; g++) {
            const int gn = col0 + wn * WN + g * 8 + ec;
            #pragma unroll
            for (int hrow = 0; hrow < 2; hrow++) {
                const int gm = row0 + wm * 32 + mt * 16 + er + hrow * 8;
                if (gm >= M) continue;
                float v0 = acc[mt][g][2 * hrow];
                float v1 = acc[mt][g][2 * hrow + 1];
                if constexpr (EPI == 1 || EPI == 2 || EPI == 3) {
                    v0 += bias[gn]; v1 += bias[gn + 1];
                }
                if constexpr (EPI == 2) { v0 = gelu_exact(v0); v1 = gelu_exact(v1); }
                if constexpr (EPI == 2 || EPI == 4) {
                    __half2 hp; hp.x = __float2half_rn(v0); hp.y = __float2half_rn(v1);
                    *(__half2*)(Ch + (size_t)gm * N + gn) = hp;
                } else if constexpr (EPI == 5) {
                    __half2 hp; hp.x = __float2half_rn(v0); hp.y = __float2half_rn(v1);
                    if (gn < CNEW) *(__half2*)(Ch  + (size_t)gm * CNEW + gn) = hp;
                    else           *(__half2*)(Ch2 + (size_t)gm * CDIM + gn - CNEW) = hp;
                } else {
                    const size_t base = (size_t)gm * N + gn;
                    if constexpr (EPI == 3) {
                        float2 rs = *(const float2*)(resid + base);
                        v0 += rs.x; v1 += rs.y;
                    }
                    float2 o; o.x = v0; o.y = v1;
                    *(float2*)(Cf + base) = o;
                }
            }
        }
    }
}

// ---------------------------------------------------------------------------
// Tensor-core attention (R16, known-good)
// ---------------------------------------------------------------------------
#define KSTR 176
#define VSTR 144

__global__ __launch_bounds__(128) void attn_tc_kernel(
        const __half* __restrict__ q, const __half* __restrict__ k,
        const __half* __restrict__ v, __half* __restrict__ oh) {
    __shared__ __align__(16) uint8_t ksm[64 * KSTR];
    __shared__ __align__(16) uint8_t vsm[64 * VSTR];
    const int bh = blockIdx.x;
    const int b = bh / NHEAD, hh = bh % NHEAD;
    const int tid = threadIdx.x, lane = tid & 31, wid = tid >> 5;
    const uint32_t ks0 = smem_u32(ksm), vs0 = smem_u32(vsm);

    const __half* kb = k + (size_t)b * MTOK * CNEW + hh * HDK;
    for (int i = tid; i < 64 * 10; i += 128) {
        int r = i / 10, cc = i % 10;
        uint4 val = make_uint4(0u, 0u, 0u, 0u);
        if (r < MTOK) val = *(const uint4*)(kb + (size_t)r * CNEW + cc * 8);
        *(uint4*)(ksm + r * KSTR + cc * 16) = val;
    }
    const __half* vb = v + (size_t)b * MTOK * CDIM + hh * HD;
    for (int i = tid; i < 64 * 8; i += 128) {
        int r = i / 8, cc = i % 8;
        uint4 val = make_uint4(0u, 0u, 0u, 0u);
        if (r < MTOK) val = *(const uint4*)(vb + (size_t)r * CDIM + cc * 8);
        *(uint4*)(vsm + r * VSTR + cc * 16) = val;
    }
    __syncthreads();

    const float scale = rsqrtf(80.0f);
    const __half* qb = q + (size_t)b * NTOK * CNEW + hh * HDK;

    for (int t = wid; t < 13; t += 4) {
        const int row0 = t * 16;
        int r0 = row0 + (lane >> 2);
        int r1 = r0 + 8;
        const int r0c = (r0 > NTOK - 1) ? NTOK - 1 : r0;
        const int r1c = (r1 > NTOK - 1) ? NTOK - 1 : r1;

        float s[8][4];
        #pragma unroll
        for (int g = 0; g < 8; g++)
            #pragma unroll
            for (int j = 0; j < 4; j++) s[g][j] = 0.f;
        #pragma unroll
        for (int kq = 0; kq < 5; kq++) {
            uint32_t a[4];
            const int c0 = kq * 16 + (lane & 3) * 2;
            a[0] = *(const uint32_t*)(qb + (size_t)r0c * CNEW + c0);
            a[1] = *(const uint32_t*)(qb + (size_t)r1c * CNEW + c0);
            a[2] = *(const uint32_t*)(qb + (size_t)r0c * CNEW + c0 + 8);
            a[3] = *(const uint32_t*)(qb + (size_t)r1c * CNEW + c0 + 8);
            #pragma unroll
            for (int g2 = 0; g2 < 4; g2++) {
                uint32_t bk[4];
                uint32_t addr = ks0 + (g2 * 16 + (lane & 7) + ((lane >> 4) << 3)) * KSTR
                              + kq * 32 + (((lane >> 3) & 1) << 4);
                ldsm_x4(bk, addr);
                mma16816(s[2*g2],   a, bk[0], bk[1]);
                mma16816(s[2*g2+1], a, bk[2], bk[3]);
            }
        }

        float mx0 = -1e30f, mx1 = -1e30f;
        #pragma unroll
        for (int g = 0; g < 8; g++) {
            const int c = g * 8 + (lane & 3) * 2;
            s[g][0] = (c     < MTOK) ? s[g][0] * scale : -1e30f;
            s[g][1] = (c + 1 < MTOK) ? s[g][1] * scale : -1e30f;
            s[g][2] = (c     < MTOK) ? s[g][2] * scale : -1e30f;
            s[g][3] = (c + 1 < MTOK) ? s[g][3] * scale : -1e30f;
            mx0 = fmaxf(mx0, fmaxf(s[g][0], s[g][1]));
            mx1 = fmaxf(mx1, fmaxf(s[g][2], s[g][3]));
        }
        #pragma unroll
        for (int off = 1; off <= 2; off <<= 1) {
            mx0 = fmaxf(mx0, __shfl_xor_sync(0xffffffffu, mx0, off));
            mx1 = fmaxf(mx1, __shfl_xor_sync(0xffffffffu, mx1, off));
        }
        float sm0 = 0.f, sm1 = 0.f;
        #pragma unroll
        for (int g = 0; g < 8; g++) {
            s[g][0] = __expf(s[g][0] - mx0);
            s[g][1] = __expf(s[g][1] - mx0);
            s[g][2] = __expf(s[g][2] - mx1);
            s[g][3] = __expf(s[g][3] - mx1);
            sm0 += s[g][0] + s[g][1];
            sm1 += s[g][2] + s[g][3];
        }
        #pragma unroll
        for (int off = 1; off <= 2; off <<= 1) {
            sm0 += __shfl_xor_sync(0xffffffffu, sm0, off);
            sm1 += __shfl_xor_sync(0xffffffffu, sm1, off);
        }
        const float inv0 = 1.f / sm0, inv1 = 1.f / sm1;

        float o[8][4];
        #pragma unroll
        for (int g = 0; g < 8; g++)
            #pragma unroll
            for (int j = 0; j < 4; j++) o[g][j] = 0.f;
        #pragma unroll
        for (int kt = 0; kt < 4; kt++) {
            uint32_t a[4];
            __half2 p;
            p.x = __float2half_rn(s[2*kt][0]);   p.y = __float2half_rn(s[2*kt][1]);
            a[0] = *(uint32_t*)&p;
            p.x = __float2half_rn(s[2*kt][2]);   p.y = __float2half_rn(s[2*kt][3]);
            a[1] = *(uint32_t*)&p;
            p.x = __float2half_rn(s[2*kt+1][0]); p.y = __float2half_rn(s[2*kt+1][1]);
            a[2] = *(uint32_t*)&p;
            p.x = __float2half_rn(s[2*kt+1][2]); p.y = __float2half_rn(s[2*kt+1][3]);
            a[3] = *(uint32_t*)&p;
            #pragma unroll
            for (int n2 = 0; n2 < 4; n2++) {
                uint32_t bv[4];
                uint32_t addr = vs0 + (kt * 16 + (lane & 15)) * VSTR
                              + n2 * 32 + ((lane >> 4) << 4);
                ldsm_x4_t(bv, addr);
                mma16816(o[2*n2],   a, bv[0], bv[1]);
                mma16816(o[2*n2+1], a, bv[2], bv[3]);
            }
        }

        #pragma unroll
        for (int g = 0; g < 8; g++) {
            const int c = g * 8 + (lane & 3) * 2;
            if (r0 < NTOK) {
                __half2 hp;
                hp.x = __float2half_rn(o[g][0] * inv0);
                hp.y = __float2half_rn(o[g][1] * inv0);
                *(__half2*)(oh + ((size_t)(b * NTOK + r0)) * CDIM + hh * HD + c) = hp;
            }
            if (r1 < NTOK) {
                __half2 hp;
                hp.x = __float2half_rn(o[g][2] * inv1);
                hp.y = __float2half_rn(o[g][3] * inv1);
                *(__half2*)(oh + ((size_t)(b * NTOK + r1)) * CDIM + hh * HD + c) = hp;
            }
        }
    }
}

// ---------------- host ----------------
static inline int cdiv(int a, int b) { return (a + b - 1) / b; }
#define SMEM_OF(BM, BN) (1024 + 3 * ((BM + BN) * RSTRIDE))

extern "C" void kernel_launch(void* const* d_in, const int* in_sizes, int n_in,
                              void* d_out, int out_size) {
    const float* x_in   = (const float*)d_in[0];
    const float* q_w    = (const float*)d_in[1];
    const float* dw_w   = (const float*)d_in[2];
    const float* dw_b   = (const float*)d_in[3];
    const float* pw_w   = (const float*)d_in[4];
    const float* pw_b   = (const float*)d_in[5];
    const float* lnr_g  = (const float*)d_in[6];
    const float* lnr_b  = (const float*)d_in[7];
    const float* k_w    = (const float*)d_in[8];
    const float* v_w    = (const float*)d_in[9];
    const float* proj_w = (const float*)d_in[10];
    const float* proj_b = (const float*)d_in[11];
    const float* ln1_g  = (const float*)d_in[12];
    const float* ln1_b  = (const float*)d_in[13];
    const float* ln2_g  = (const float*)d_in[14];
    const float* ln2_b  = (const float*)d_in[15];
    const float* fc1_w  = (const float*)d_in[16];
    const float* fc1_b  = (const float*)d_in[17];
    const float* fc2_w  = (const float*)d_in[18];
    const float* fc2_b  = (const float*)d_in[19];

    float* xcur = (float*)d_out;

    float* p_r0;
    __half *p_yh, *p_rch, *p_rh, *p_qh, *p_kh, *p_vh, *p_oh, *p_hh;
    __half *wq, *wpw, *wkv, *wp, *w1, *w2;
    cudaGetSymbolAddress((void**)&p_r0, g_r0);
    cudaGetSymbolAddress((void**)&p_yh, g_yh);   cudaGetSymbolAddress((void**)&p_rch, g_rch);
    cudaGetSymbolAddress((void**)&p_rh, g_rh);
    cudaGetSymbolAddress((void**)&p_qh, g_qh);   cudaGetSymbolAddress((void**)&p_kh, g_kh);
    cudaGetSymbolAddress((void**)&p_vh, g_vh);
    cudaGetSymbolAddress((void**)&p_oh, g_oh);   cudaGetSymbolAddress((void**)&p_hh, g_hh);
    cudaGetSymbolAddress((void**)&wq, g_wq);     cudaGetSymbolAddress((void**)&wpw, g_wpw);
    cudaGetSymbolAddress((void**)&wkv, g_wkv);
    cudaGetSymbolAddress((void**)&wp, g_wp);     cudaGetSymbolAddress((void**)&w1, g_w1);
    cudaGetSymbolAddress((void**)&w2, g_w2);

    cudaFuncSetAttribute(tcmm_kernel<64,64,2,2,1>,    cudaFuncAttributeMaxDynamicSharedMemorySize, SMEM_OF(64,64));
    cudaFuncSetAttribute(tcmm_kernel<64,64,2,2,5>,    cudaFuncAttributeMaxDynamicSharedMemorySize, SMEM_OF(64,64));
    cudaFuncSetAttribute(tcmm_kernel<128,64,4,2,4>,   cudaFuncAttributeMaxDynamicSharedMemorySize, SMEM_OF(128,64));
    cudaFuncSetAttribute(tcmm_kernel<128,128,4,2,2>,  cudaFuncAttributeMaxDynamicSharedMemorySize, SMEM_OF(128,128));
    cudaFuncSetAttribute(tcmm_kernel<128,128,4,2,3>,  cudaFuncAttributeMaxDynamicSharedMemorySize, SMEM_OF(128,128));

    // weight transpose, all layers batched via grid.z
    wsplit_kernel<<<dim3(CNEW/32,   CDIM/32,   LAYERS), 256>>>(q_w,    wq,  CDIM,   CNEW, (size_t)CDIM*CNEW);
    wsplit_kernel<<<dim3(CNEW/32,   CDIM/32,   LAYERS), 256>>>(pw_w,   wpw, CDIM,   CNEW, (size_t)CDIM*CNEW);
    wsplit_kernel<<<dim3(CNEW/32,   CNEW/32,   LAYERS), 256>>>(k_w,    wkv, CNEW,   CNEW, (size_t)NKV*CNEW);
    wsplit_kernel<<<dim3(CDIM/32,   CNEW/32,   LAYERS), 256>>>(v_w,    wkv + (size_t)CNEW*CNEW,
                                                               CNEW,   CDIM, (size_t)NKV*CNEW);
    wsplit_kernel<<<dim3(CDIM/32,   CDIM/32,   LAYERS), 256>>>(proj_w, wp,  CDIM,   CDIM, (size_t)CDIM*CDIM);
    wsplit_kernel<<<dim3(HIDDIM/32, CDIM/32,   LAYERS), 256>>>(fc1_w,  w1,  CDIM,   HIDDIM, (size_t)CDIM*HIDDIM);
    wsplit_kernel<<<dim3(CDIM/32,   HIDDIM/32, LAYERS), 256>>>(fc2_w,  w2,  HIDDIM, CDIM, (size_t)HIDDIM*CDIM);

    for (int l = 0; l < LAYERS; l++) {
        const float* xin = (l == 0) ? x_in : xcur;
        ln_kernel<CDIM,0><<<cdiv(ROWS_X,8), 256>>>(xin, p_yh,
            ln1_g + l*CDIM, ln1_b + l*CDIM, 1e-6f, ROWS_X);
        dwconv_kernel<<<dim3(MTOK, BATCH), 256>>>(p_yh, dw_w + (size_t)l*CDIM*4,
                                                  dw_b + l*CDIM, p_rch);
        tcmm_kernel<64,64,2,2,1><<<dim3(CNEW/64, ROWS_R/64), 128, SMEM_OF(64,64)>>>(
            p_rch, wpw + (size_t)l*CNEW*CDIM,
            pw_b + l*CNEW, nullptr, p_r0, nullptr, nullptr, ROWS_R, CNEW, CDIM);
        ln_kernel<CNEW,1><<<cdiv(ROWS_R,8), 256>>>(p_r0, p_rh,
            lnr_g + l*CNEW, lnr_b + l*CNEW, 1e-5f, ROWS_R);
        tcmm_kernel<128,64,4,2,4><<<dim3(CNEW/64, ROWS_X/128), 256, SMEM_OF(128,64)>>>(
            p_yh, wq + (size_t)l*CNEW*CDIM,
            nullptr, nullptr, nullptr, p_qh, nullptr, ROWS_X, CNEW, CDIM);
        tcmm_kernel<64,64,2,2,5><<<dim3(NKV/64, ROWS_R/64), 128, SMEM_OF(64,64)>>>(
            p_rh, wkv + (size_t)l*NKV*CNEW,
            nullptr, nullptr, nullptr, p_kh, p_vh, ROWS_R, NKV, CNEW);
        attn_tc_kernel<<<BATCH*NHEAD, 128>>>(p_qh, p_kh, p_vh, p_oh);
        tcmm_kernel<128,128,4,2,3><<<dim3(CDIM/128, ROWS_X/128), 256, SMEM_OF(128,128)>>>(
            p_oh, wp + (size_t)l*CDIM*CDIM,
            proj_b + l*CDIM, xin, xcur, nullptr, nullptr, ROWS_X, CDIM, CDIM);
        ln_kernel<CDIM,0><<<cdiv(ROWS_X,8), 256>>>(xcur, p_yh,
            ln2_g + l*CDIM, ln2_b + l*CDIM, 1e-6f, ROWS_X);
        tcmm_kernel<128,128,4,2,2><<<dim3(HIDDIM/128, ROWS_X/128), 256, SMEM_OF(128,128)>>>(
            p_yh, w1 + (size_t)l*HIDDIM*CDIM,
            fc1_b + l*HIDDIM, nullptr, nullptr, p_hh, nullptr, ROWS_X, HIDDIM, CDIM);
        tcmm_kernel<128,128,4,2,3><<<dim3(CDIM/128, ROWS_X/128), 256, SMEM_OF(128,128)>>>(
            p_hh, w2 + (size_t)l*CDIM*HIDDIM,
            fc2_b + l*CDIM, xcur, xcur, nullptr, nullptr, ROWS_X, CDIM, HIDDIM);
    }
}